// round 13
// baseline (speedup 1.0000x reference)
#include <cuda_runtime.h>
#include <cuda_bf16.h>
#include <math.h>
#include <stdint.h>

constexpr int SEQ  = 1576;   // T*N tokens
constexpr int DIM  = 768;
constexpr int NHEAD = 12;
constexpr int HD   = 64;
constexpr int TFR  = 8;      // frames
constexpr int NTOK = 197;    // tokens per frame
constexpr int NPAT = 196;
constexpr int MLPD = 3072;
constexpr int QKVD = 2304;
constexpr float ASCALE = 0.125f;

// ---------------- scratch (no allocation allowed) ----------------
__device__ float g_emb[1568 * 768];
__device__ float g_h[SEQ * DIM];
__device__ float g_qkv[SEQ * QKVD];
__device__ float g_vmean[NHEAD * TFR * HD];
__device__ unsigned short g_p_hi[1568 * 768],  g_p_lo[1568 * 768];
__device__ unsigned short g_a_hi[SEQ * DIM],   g_a_lo[SEQ * DIM];
__device__ unsigned short g_o_hi[SEQ * DIM],   g_o_lo[SEQ * DIM];
__device__ unsigned short g_m_hi[SEQ * MLPD],  g_m_lo[SEQ * MLPD];
__device__ unsigned short g_wp_hi[DIM * DIM],        g_wp_lo[DIM * DIM];
__device__ unsigned short g_qkvT_hi[12 * QKVD * DIM], g_qkvT_lo[12 * QKVD * DIM];
__device__ unsigned short g_projT_hi[12 * DIM * DIM], g_projT_lo[12 * DIM * DIM];
__device__ unsigned short g_fc1T_hi[12 * MLPD * DIM], g_fc1T_lo[12 * MLPD * DIM];
__device__ unsigned short g_fc2T_hi[12 * DIM * MLPD], g_fc2T_lo[12 * DIM * MLPD];

// ================= helpers =================
__device__ __forceinline__ uint32_t smem_u32(const void* p) {
    uint32_t a;
    asm("{ .reg .u64 t; cvta.to.shared.u64 t, %1; cvt.u32.u64 %0, t; }" : "=r"(a) : "l"(p));
    return a;
}
__device__ __forceinline__ void split1(float v, unsigned short& hi, unsigned short& lo) {
    __nv_bfloat16 h = __float2bfloat16(v);
    __nv_bfloat16 l = __float2bfloat16(v - __bfloat162float(h));
    hi = __bfloat16_as_ushort(h);
    lo = __bfloat16_as_ushort(l);
}

#define LDM4(r, addr) \
    asm volatile("ldmatrix.sync.aligned.m8n8.x4.shared.b16 {%0,%1,%2,%3}, [%4];" \
        : "=r"((r)[0]), "=r"((r)[1]), "=r"((r)[2]), "=r"((r)[3]) : "r"(addr))

#define MMA_BF16(c, a, b0, b1) \
    asm volatile("mma.sync.aligned.m16n8k16.row.col.f32.bf16.bf16.f32 " \
        "{%0,%1,%2,%3}, {%4,%5,%6,%7}, {%8,%9}, {%0,%1,%2,%3};" \
        : "+f"((c)[0]), "+f"((c)[1]), "+f"((c)[2]), "+f"((c)[3]) \
        : "r"((a)[0]), "r"((a)[1]), "r"((a)[2]), "r"((a)[3]), "r"(b0), "r"(b1))

#define CPA16(dst, src, sz) \
    asm volatile("cp.async.cg.shared.global [%0], [%1], 16, %2;" \
        :: "r"(dst), "l"(src), "r"(sz))
#define CPA_COMMIT() asm volatile("cp.async.commit_group;")
#define CPA_WAIT1()  asm volatile("cp.async.wait_group 1;")

// ---------------- transpose + split: fp32 [K,N] -> bf16 hi/lo [N,K] ----------------
__global__ void transpose_split_kernel(const float* __restrict__ in,
        unsigned short* __restrict__ ohi, unsigned short* __restrict__ olo, int K, int N) {
    __shared__ float t[32][33];
    size_t base = (size_t)blockIdx.z * K * N;
    int n0 = blockIdx.x * 32, k0 = blockIdx.y * 32;
    int tx = threadIdx.x, ty = threadIdx.y;
    #pragma unroll
    for (int j = 0; j < 32; j += 8)
        t[ty + j][tx] = in[base + (size_t)(k0 + ty + j) * N + n0 + tx];
    __syncthreads();
    #pragma unroll
    for (int j = 0; j < 32; j += 8) {
        unsigned short hi, lo;
        split1(t[tx][ty + j], hi, lo);
        size_t o = base + (size_t)(n0 + ty + j) * K + k0 + tx;
        ohi[o] = hi; olo[o] = lo;
    }
}

// ---------------- elementwise split ----------------
__global__ void split_kernel(const float* __restrict__ in,
        unsigned short* __restrict__ hi, unsigned short* __restrict__ lo, int n) {
    int i = blockIdx.x * blockDim.x + threadIdx.x;
    if (i >= n) return;
    split1(in[i], hi[i], lo[i]);
}

// ===================================================================================
// bf16x3 MMA GEMM (exact best configuration)
// ===================================================================================
constexpr int RS = 80;
constexpr int NSTG = 3;
constexpr int AL_OFF = 64 * RS;
constexpr int BH_OFF = 2 * 64 * RS;
constexpr int BL_OFF = BH_OFF + 128 * RS;
constexpr int STG    = BH_OFF + 2 * 128 * RS;   // 30720

__device__ __forceinline__ void load_stage(uint32_t sb,
        const unsigned short* __restrict__ Ahi, const unsigned short* __restrict__ Alo,
        const unsigned short* __restrict__ Bhi, const unsigned short* __restrict__ Blo,
        int row0, int col0, int K, int k0, int M, int tid) {
    int r = tid >> 2, ch = tid & 3;
    uint32_t doff = (uint32_t)(r * RS + ch * 16);
    size_t asrc = (size_t)(row0 + r) * K + k0 + ch * 8;
    int av = (row0 + r < M) ? 16 : 0;
    CPA16(sb + doff, Ahi + asrc, av);
    CPA16(sb + AL_OFF + doff, Alo + asrc, av);
    size_t b0 = (size_t)(col0 + r) * K + k0 + ch * 8;
    size_t b1 = (size_t)(col0 + 64 + r) * K + k0 + ch * 8;
    CPA16(sb + BH_OFF + doff, Bhi + b0, 16);
    CPA16(sb + BH_OFF + doff + 64 * RS, Bhi + b1, 16);
    CPA16(sb + BL_OFF + doff, Blo + b0, 16);
    CPA16(sb + BL_OFF + doff + 64 * RS, Blo + b1, 16);
    CPA_COMMIT();
}

__global__ void __launch_bounds__(256, 2) mma_gemm(
        const unsigned short* __restrict__ Ahi, const unsigned short* __restrict__ Alo,
        const unsigned short* __restrict__ Bhi, const unsigned short* __restrict__ Blo,
        const float* __restrict__ bias, const float* __restrict__ res,
        float* __restrict__ C, unsigned short* __restrict__ Chi,
        unsigned short* __restrict__ Clo,
        int M, int N, int K, int act) {
    extern __shared__ __align__(128) char sm[];
    const int tid = threadIdx.x;
    const int lane = tid & 31, wid = tid >> 5;
    const int wm = wid & 1, wn = wid >> 1;
    const int row0 = blockIdx.y * 64, col0 = blockIdx.x * 128;
    const uint32_t smb = smem_u32(sm);

    const int a_row = ((lane >> 3) & 1) * 8 + (lane & 7);
    const int a_kb  = (lane >> 4) * 16;
    const int b_row = (lane >> 4) * 8 + (lane & 7);
    const int b_kb  = ((lane >> 3) & 1) * 16;

    float c[2][4][4];
    #pragma unroll
    for (int i = 0; i < 2; i++)
        #pragma unroll
        for (int j = 0; j < 4; j++)
            #pragma unroll
            for (int k = 0; k < 4; k++) c[i][j][k] = 0.f;

    const int nk = K >> 5;
    load_stage(smb, Ahi, Alo, Bhi, Blo, row0, col0, K, 0, M, tid);
    load_stage(smb + STG, Ahi, Alo, Bhi, Blo, row0, col0, K, 32, M, tid);

    int buf = 0;
    for (int it = 0; it < nk; it++) {
        CPA_WAIT1();
        __syncthreads();
        if (it + 2 < nk) {
            int nb = buf + 2; if (nb >= NSTG) nb -= NSTG;
            load_stage(smb + (uint32_t)nb * STG, Ahi, Alo, Bhi, Blo,
                       row0, col0, K, (it + 2) << 5, M, tid);
        }
        uint32_t sb = smb + (uint32_t)buf * STG;
        #pragma unroll
        for (int kk = 0; kk < 2; kk++) {
            uint32_t bh[8], bl[8];
            #pragma unroll
            for (int nip = 0; nip < 2; nip++) {
                uint32_t baddr = sb + BH_OFF + (wn * 32 + nip * 16 + b_row) * RS + b_kb + kk * 32;
                LDM4(&bh[nip * 4], baddr);
                LDM4(&bl[nip * 4], baddr + (BL_OFF - BH_OFF));
            }
            #pragma unroll
            for (int mi = 0; mi < 2; mi++) {
                uint32_t ah[4], al[4];
                uint32_t aaddr = sb + (wm * 32 + mi * 16 + a_row) * RS + a_kb + kk * 32;
                LDM4(ah, aaddr);
                LDM4(al, aaddr + AL_OFF);
                #pragma unroll
                for (int ni = 0; ni < 4; ni++) {
                    uint32_t b0h = bh[(ni >> 1) * 4 + (ni & 1) * 2];
                    uint32_t b1h = bh[(ni >> 1) * 4 + (ni & 1) * 2 + 1];
                    uint32_t b0l = bl[(ni >> 1) * 4 + (ni & 1) * 2];
                    uint32_t b1l = bl[(ni >> 1) * 4 + (ni & 1) * 2 + 1];
                    MMA_BF16(c[mi][ni], ah, b0h, b1h);
                    MMA_BF16(c[mi][ni], ah, b0l, b1l);
                    MMA_BF16(c[mi][ni], al, b0h, b1h);
                }
            }
        }
        buf++; if (buf >= NSTG) buf = 0;
    }

    // ---- epilogue ----
    const int g = lane >> 2, t = lane & 3;
    #pragma unroll
    for (int mi = 0; mi < 2; mi++) {
        #pragma unroll
        for (int ni = 0; ni < 4; ni++) {
            int col = col0 + wn * 32 + ni * 8 + t * 2;
            float2 bb = bias ? *(const float2*)(bias + col) : make_float2(0.f, 0.f);
            #pragma unroll
            for (int half = 0; half < 2; half++) {
                int gm = row0 + wm * 32 + mi * 16 + g + half * 8;
                if (gm >= M) continue;
                float v0 = c[mi][ni][half * 2 + 0] + bb.x;
                float v1 = c[mi][ni][half * 2 + 1] + bb.y;
                if (act) {
                    v0 = 0.5f * v0 * (1.f + erff(v0 * 0.70710678118f));
                    v1 = 0.5f * v1 * (1.f + erff(v1 * 0.70710678118f));
                }
                if (res) {
                    float2 rv = *(const float2*)(res + (size_t)gm * N + col);
                    v0 += rv.x; v1 += rv.y;
                }
                size_t o = (size_t)gm * N + col;
                if (Chi) {
                    unsigned short h0, l0, h1, l1;
                    split1(v0, h0, l0);
                    split1(v1, h1, l1);
                    *(uint32_t*)(Chi + o) = (uint32_t)h0 | ((uint32_t)h1 << 16);
                    *(uint32_t*)(Clo + o) = (uint32_t)l0 | ((uint32_t)l1 << 16);
                } else {
                    *(float2*)(C + o) = make_float2(v0, v1);
                }
            }
        }
    }
}

// ---------------- patch extraction -> bf16 hi/lo ----------------
__global__ void patch_kernel(const float* __restrict__ x,
        unsigned short* __restrict__ Phi, unsigned short* __restrict__ Plo) {
    int idx = blockIdx.x * blockDim.x + threadIdx.x;
    if (idx >= 1568 * 768) return;
    int m = idx / 768, kcol = idx % 768;
    int t = m / 196, n = m % 196;
    int hp = n / 14, wp = n % 14;
    int c = kcol / 256, rem = kcol % 256;
    int ii = rem / 16, jj = rem % 16;
    float v = x[((t * 3 + c) * 224 + hp * 16 + ii) * 224 + wp * 16 + jj];
    split1(v, Phi[idx], Plo[idx]);
}

// ---------------- assemble h ----------------
__global__ void assemble_kernel(const float* __restrict__ emb, const float* __restrict__ cls,
                                const float* __restrict__ pos, float* __restrict__ h) {
    int idx = blockIdx.x * blockDim.x + threadIdx.x;
    if (idx >= SEQ * DIM) return;
    int m = idx / DIM, dd = idx % DIM;
    int t = m / NTOK, r = m % NTOK;
    float v;
    if (r == 0) {
        v = cls[dd] + pos[dd];
    } else {
        int pp = r - 1;
        int f = pp * DIM + dd;
        int n = f % NPAT, dc = f / NPAT;
        v = emb[(t * NPAT + n) * DIM + dc] + pos[(1 + pp) * DIM + dd];
    }
    h[idx] = v;
}

// ---------------- block reduction ----------------
__device__ __forceinline__ float block_sum256(float v, float* sh) {
    #pragma unroll
    for (int o = 16; o; o >>= 1) v += __shfl_xor_sync(0xffffffffu, v, o);
    if ((threadIdx.x & 31) == 0) sh[threadIdx.x >> 5] = v;
    __syncthreads();
    float t = 0.f;
    #pragma unroll
    for (int i = 0; i < 8; i++) t += sh[i];
    __syncthreads();
    return t;
}

// ---------------- LayerNorm -> bf16 hi/lo ----------------
__global__ void ln_split_kernel(const float* __restrict__ x, const float* __restrict__ g,
        const float* __restrict__ b, unsigned short* __restrict__ yhi,
        unsigned short* __restrict__ ylo) {
    __shared__ float sh[8];
    int row = blockIdx.x, tid = threadIdx.x;
    const float* xr = x + (size_t)row * DIM;
    float v0 = xr[tid], v1 = xr[tid + 256], v2 = xr[tid + 512];
    float mean = block_sum256(v0 + v1 + v2, sh) * (1.f / DIM);
    float d0 = v0 - mean, d1 = v1 - mean, d2 = v2 - mean;
    float var = block_sum256(d0 * d0 + d1 * d1 + d2 * d2, sh) * (1.f / DIM);
    float inv = rsqrtf(var + 1e-5f);
    size_t o = (size_t)row * DIM + tid;
    float y0 = d0 * inv * g[tid]       + b[tid];
    float y1 = d1 * inv * g[tid + 256] + b[tid + 256];
    float y2 = d2 * inv * g[tid + 512] + b[tid + 512];
    split1(y0, yhi[o],       ylo[o]);
    split1(y1, yhi[o + 256], ylo[o + 256]);
    split1(y2, yhi[o + 512], ylo[o + 512]);
}

// ---------------- final LayerNorm (fp32 out) ----------------
__global__ void ln_kernel(const float* __restrict__ x, const float* __restrict__ g,
                          const float* __restrict__ b, float* __restrict__ y) {
    __shared__ float sh[8];
    int row = blockIdx.x, tid = threadIdx.x;
    const float* xr = x + (size_t)row * DIM;
    float v0 = xr[tid], v1 = xr[tid + 256], v2 = xr[tid + 512];
    float mean = block_sum256(v0 + v1 + v2, sh) * (1.f / DIM);
    float d0 = v0 - mean, d1 = v1 - mean, d2 = v2 - mean;
    float var = block_sum256(d0 * d0 + d1 * d1 + d2 * d2, sh) * (1.f / DIM);
    float inv = rsqrtf(var + 1e-5f);
    float* yr = y + (size_t)row * DIM;
    yr[tid]       = d0 * inv * g[tid]       + b[tid];
    yr[tid + 256] = d1 * inv * g[tid + 256] + b[tid + 256];
    yr[tid + 512] = d2 * inv * g[tid + 512] + b[tid + 512];
}

// ---------------- temporal v-mean ----------------
__global__ void vmean_kernel(const float* __restrict__ qkv, float* __restrict__ vmean) {
    int ht = blockIdx.x;
    int t = ht % TFR, h = ht / TFR;
    int d = threadIdx.x;
    float s = 0.f;
    for (int n = 0; n < NTOK; n++)
        s += qkv[(size_t)(t * NTOK + n) * QKVD + 2 * DIM + h * HD + d];
    vmean[ht * HD + d] = s * (1.f / NTOK);
}

// ---------------- attention, templated; warps own ceil(QBT/NWARP) queries ----------
template <int QBT, int NTHR, int KCH>
__global__ void __launch_bounds__(NTHR) attn_kernel(
        const float* __restrict__ qkv, const float* __restrict__ vmean,
        unsigned short* __restrict__ ohi, unsigned short* __restrict__ olo,
        int keyLen, int keyLenP, int numSeg) {
    constexpr int NWARP = NTHR / 32;
    constexpr int NPART = NWARP;
    constexpr int NREP  = (QBT + NWARP - 1) / NWARP;
    extern __shared__ float smf[];
    float* qs  = smf;                        // QBT*HD
    float* sc  = smf + QBT * HD;             // QBT*keyLenP
    float* red = sc + QBT * keyLenP;         // NPART*QBT*HD
    __shared__ float wsum[QBT];
    int tid = threadIdx.x;
    int hseg = blockIdx.y;
    int h = hseg / numSeg, seg = hseg % numSeg;
    int base = seg * keyLen;
    int q0 = blockIdx.x * QBT;
    int nq = min(QBT, keyLen - q0);

    for (int i = tid; i < QBT * HD; i += NTHR) {
        int qi = i / HD, d = i % HD;
        qs[i] = (qi < nq) ? qkv[(size_t)(base + q0 + qi) * QKVD + h * HD + d] : 0.f;
    }
    __syncthreads();

    // ---- scores ----
    const int nkb = (keyLen + KCH - 1) / KCH;
    for (int kb = tid; kb < nkb; kb += NTHR) {
        int kk = kb * KCH;
        float acc[QBT][KCH];
        #pragma unroll
        for (int qi = 0; qi < QBT; qi++)
            #pragma unroll
            for (int c = 0; c < KCH; c++) acc[qi][c] = 0.f;
        const float* kbase0 = qkv + (size_t)(base + kk) * QKVD + DIM + h * HD;
        int voff[KCH];
        #pragma unroll
        for (int c = 0; c < KCH; c++) voff[c] = (kk + c < keyLen) ? c : 0;
        #pragma unroll 4
        for (int j = 0; j < 16; j++) {
            float4 kf[KCH];
            #pragma unroll
            for (int c = 0; c < KCH; c++)
                kf[c] = *(const float4*)(kbase0 + (size_t)voff[c] * QKVD + j * 4);
            #pragma unroll
            for (int qi = 0; qi < QBT; qi++) {
                float4 q = *(const float4*)(qs + qi * HD + j * 4);
                #pragma unroll
                for (int c = 0; c < KCH; c++)
                    acc[qi][c] += q.x * kf[c].x + q.y * kf[c].y
                                + q.z * kf[c].z + q.w * kf[c].w;
            }
        }
        #pragma unroll
        for (int qi = 0; qi < QBT; qi++) {
            float* dst = sc + qi * keyLenP + kk;
            if (kk + KCH <= keyLen) {
                #pragma unroll
                for (int c = 0; c < KCH; c++) dst[c] = acc[qi][c] * ASCALE;
            } else {
                for (int c = 0; c < KCH; c++)
                    if (kk + c < keyLen) dst[c] = acc[qi][c] * ASCALE;
            }
        }
    }
    __syncthreads();

    // ---- softmax ----
    int w = tid >> 5, lane = tid & 31;
    #pragma unroll
    for (int rep = 0; rep < NREP; rep++) {
        int q = w + rep * NWARP;
        if (q < nq) {
            float mx = -1e30f;
            for (int kk = lane; kk < keyLen; kk += 32) mx = fmaxf(mx, sc[q * keyLenP + kk]);
            #pragma unroll
            for (int off = 16; off; off >>= 1) mx = fmaxf(mx, __shfl_xor_sync(0xffffffffu, mx, off));
            float sum = 0.f;
            for (int kk = lane; kk < keyLen; kk += 32) {
                float e = __expf(sc[q * keyLenP + kk] - mx);
                sc[q * keyLenP + kk] = e;
                sum += e;
            }
            #pragma unroll
            for (int off = 16; off; off >>= 1) sum += __shfl_xor_sync(0xffffffffu, sum, off);
            if (lane == 0) wsum[q] = sum;
        }
    }
    __syncthreads();

    // ---- AV: NPART key-partitions (one per warp), float2 V loads ----
    {
        int d2 = lane;
        int part = w;
        float2 acc[QBT];
        #pragma unroll
        for (int qi = 0; qi < QBT; qi++) acc[qi] = make_float2(0.f, 0.f);
        const float* vbase = qkv + 2 * DIM + h * HD + d2 * 2;
        for (int kk = part; kk < keyLen; kk += NPART) {
            float2 v = *(const float2*)(vbase + (size_t)(base + kk) * QKVD);
            #pragma unroll
            for (int qi = 0; qi < QBT; qi++) {
                float p = sc[qi * keyLenP + kk];
                acc[qi].x += p * v.x;
                acc[qi].y += p * v.y;
            }
        }
        #pragma unroll
        for (int qi = 0; qi < QBT; qi++)
            *(float2*)(red + (part * QBT + qi) * HD + d2 * 2) = acc[qi];
        __syncthreads();
        #pragma unroll
        for (int rep = 0; rep < NREP; rep++) {
            int qi = w + rep * NWARP;
            if (qi < nq) {
                float sx = 0.f, sy = 0.f;
                #pragma unroll
                for (int pp = 0; pp < NPART; pp++) {
                    float2 r = *(const float2*)(red + (pp * QBT + qi) * HD + d2 * 2);
                    sx += r.x; sy += r.y;
                }
                float inv = 1.f / wsum[qi];
                sx *= inv; sy *= inv;
                if (vmean) {
                    sx += vmean[hseg * HD + d2 * 2];
                    sy += vmean[hseg * HD + d2 * 2 + 1];
                }
                size_t o = (size_t)(base + q0 + qi) * DIM + h * HD + d2 * 2;
                split1(sx, ohi[o],     olo[o]);
                split1(sy, ohi[o + 1], olo[o + 1]);
            }
        }
    }
}

// ---------------- host ----------------
static void run_mma(const unsigned short* Ahi, const unsigned short* Alo,
                    const unsigned short* Bhi, const unsigned short* Blo,
                    const float* bias, const float* res, float* C,
                    unsigned short* Chi, unsigned short* Clo,
                    int M, int N, int K, int act) {
    dim3 grid(N / 128, (M + 63) / 64);
    mma_gemm<<<grid, 256, NSTG * STG>>>(Ahi, Alo, Bhi, Blo, bias, res, C, Chi, Clo, M, N, K, act);
}

extern "C" void kernel_launch(void* const* d_in, const int* in_sizes, int n_in,
                              void* d_out, int out_size) {
    const float* x       = (const float*)d_in[0];
    const float* W_patch = (const float*)d_in[1];
    const float* b_patch = (const float*)d_in[2];
    const float* cls     = (const float*)d_in[3];
    const float* pos     = (const float*)d_in[4];
    const float* ln1_g   = (const float*)d_in[5];
    const float* ln1_b   = (const float*)d_in[6];
    const float* qkv_w   = (const float*)d_in[7];
    const float* qkv_b   = (const float*)d_in[8];
    const float* proj_w  = (const float*)d_in[9];
    const float* proj_b  = (const float*)d_in[10];
    const float* ln2_g   = (const float*)d_in[11];
    const float* ln2_b   = (const float*)d_in[12];
    const float* fc1_w   = (const float*)d_in[13];
    const float* fc1_b   = (const float*)d_in[14];
    const float* fc2_w   = (const float*)d_in[15];
    const float* fc2_b   = (const float*)d_in[16];
    const float* lnf_g   = (const float*)d_in[17];
    const float* lnf_b   = (const float*)d_in[18];

    float *emb_, *h_, *qkv_, *vm_;
    unsigned short *pH, *pL, *aH, *aL, *oH, *oL, *mH, *mL;
    unsigned short *wpH, *wpL, *qkH, *qkL, *prH, *prL, *f1H, *f1L, *f2H, *f2L;
    cudaGetSymbolAddress((void**)&emb_, g_emb);
    cudaGetSymbolAddress((void**)&h_,   g_h);
    cudaGetSymbolAddress((void**)&qkv_, g_qkv);
    cudaGetSymbolAddress((void**)&vm_,  g_vmean);
    cudaGetSymbolAddress((void**)&pH, g_p_hi);   cudaGetSymbolAddress((void**)&pL, g_p_lo);
    cudaGetSymbolAddress((void**)&aH, g_a_hi);   cudaGetSymbolAddress((void**)&aL, g_a_lo);
    cudaGetSymbolAddress((void**)&oH, g_o_hi);   cudaGetSymbolAddress((void**)&oL, g_o_lo);
    cudaGetSymbolAddress((void**)&mH, g_m_hi);   cudaGetSymbolAddress((void**)&mL, g_m_lo);
    cudaGetSymbolAddress((void**)&wpH, g_wp_hi); cudaGetSymbolAddress((void**)&wpL, g_wp_lo);
    cudaGetSymbolAddress((void**)&qkH, g_qkvT_hi); cudaGetSymbolAddress((void**)&qkL, g_qkvT_lo);
    cudaGetSymbolAddress((void**)&prH, g_projT_hi); cudaGetSymbolAddress((void**)&prL, g_projT_lo);
    cudaGetSymbolAddress((void**)&f1H, g_fc1T_hi); cudaGetSymbolAddress((void**)&f1L, g_fc1T_lo);
    cudaGetSymbolAddress((void**)&f2H, g_fc2T_hi); cudaGetSymbolAddress((void**)&f2L, g_fc2T_lo);

    cudaFuncSetAttribute(mma_gemm, cudaFuncAttributeMaxDynamicSharedMemorySize, NSTG * STG);

    // spatial: QBT=16, 128 thr, KCH=2, keyLen=197 (pad 200); NPART=4
    size_t smem_sp = (size_t)(16 * HD + 16 * 200 + 4 * 16 * HD) * sizeof(float);   // ~33 KB
    // joint: QBT=20, 512 thr, KCH=2, keyLen=SEQ; NPART=16
    size_t smem_joint = (size_t)(20 * HD + 20 * SEQ + 16 * 20 * HD) * sizeof(float); // ~213 KB
    cudaFuncSetAttribute((const void*)attn_kernel<20, 512, 2>,
                         cudaFuncAttributeMaxDynamicSharedMemorySize, (int)smem_joint);
    cudaFuncSetAttribute((const void*)attn_kernel<16, 128, 2>,
                         cudaFuncAttributeMaxDynamicSharedMemorySize, (int)smem_sp);

    patch_kernel<<<(1568 * 768 + 255) / 256, 256>>>(x, pH, pL);                       // 0
    split_kernel<<<(DIM * DIM + 255) / 256, 256>>>(W_patch, wpH, wpL, DIM * DIM);     // 1
    dim3 tb(32, 8);
    transpose_split_kernel<<<dim3(QKVD / 32, DIM / 32, 12), tb>>>(qkv_w, qkH, qkL, DIM, QKVD); // 2
    run_mma(pH, pL, wpH, wpL, b_patch, nullptr, emb_, nullptr, nullptr, 1568, 768, 768, 0);    // 3 <- profiled
    transpose_split_kernel<<<dim3(DIM / 32,  DIM / 32, 12), tb>>>(proj_w, prH, prL, DIM, DIM);
    transpose_split_kernel<<<dim3(MLPD / 32, DIM / 32, 12), tb>>>(fc1_w,  f1H, f1L, DIM, MLPD);
    transpose_split_kernel<<<dim3(DIM / 32, MLPD / 32, 12), tb>>>(fc2_w,  f2H, f2L, MLPD, DIM);
    assemble_kernel<<<(SEQ * DIM + 255) / 256, 256>>>(emb_, cls, pos, h_);

    for (int i = 0; i < 12; i++) {
        ln_split_kernel<<<SEQ, 256>>>(h_, ln1_g + i * DIM, ln1_b + i * DIM, aH, aL);
        run_mma(aH, aL, qkH + (size_t)i * QKVD * DIM, qkL + (size_t)i * QKVD * DIM,
                qkv_b + i * QKVD, nullptr, qkv_, nullptr, nullptr, SEQ, QKVD, DIM, 0);
        if ((i & 1) == 0) {
            vmean_kernel<<<NHEAD * TFR, HD>>>(qkv_, vm_);
            dim3 g((NTOK + 15) / 16, NHEAD * TFR);
            attn_kernel<16, 128, 2><<<g, 128, smem_sp>>>(qkv_, vm_, oH, oL, NTOK, 200, TFR);
        } else {
            dim3 g((SEQ + 19) / 20, NHEAD);
            attn_kernel<20, 512, 2><<<g, 512, smem_joint>>>(qkv_, nullptr, oH, oL, SEQ, SEQ, 1);
        }
        run_mma(oH, oL, prH + (size_t)i * DIM * DIM, prL + (size_t)i * DIM * DIM,
                proj_b + i * DIM, h_, h_, nullptr, nullptr, SEQ, DIM, DIM, 0);
        ln_split_kernel<<<SEQ, 256>>>(h_, ln2_g + i * DIM, ln2_b + i * DIM, aH, aL);
        run_mma(aH, aL, f1H + (size_t)i * MLPD * DIM, f1L + (size_t)i * MLPD * DIM,
                fc1_b + i * MLPD, nullptr, nullptr, mH, mL, SEQ, MLPD, DIM, 1);
        run_mma(mH, mL, f2H + (size_t)i * DIM * MLPD, f2L + (size_t)i * DIM * MLPD,
                fc2_b + i * DIM, h_, h_, nullptr, nullptr, SEQ, DIM, MLPD, 0);
    }

    ln_kernel<<<SEQ, 256>>>(h_, lnf_g, lnf_b, (float*)d_out);
}

// round 14
// speedup vs baseline: 1.0301x; 1.0301x over previous
#include <cuda_runtime.h>
#include <cuda_bf16.h>
#include <math.h>
#include <stdint.h>

constexpr int SEQ  = 1576;   // T*N tokens
constexpr int DIM  = 768;
constexpr int NHEAD = 12;
constexpr int HD   = 64;
constexpr int TFR  = 8;      // frames
constexpr int NTOK = 197;    // tokens per frame
constexpr int NPAT = 196;
constexpr int MLPD = 3072;
constexpr int QKVD = 2304;
constexpr float ASCALE = 0.125f;

// ---------------- scratch (no allocation allowed) ----------------
__device__ float g_emb[1568 * 768];
__device__ float g_h[SEQ * DIM];
__device__ float g_qkv[SEQ * QKVD];
__device__ unsigned short g_p_hi[1568 * 768],  g_p_lo[1568 * 768];
__device__ unsigned short g_a_hi[SEQ * DIM],   g_a_lo[SEQ * DIM];
__device__ unsigned short g_o_hi[SEQ * DIM],   g_o_lo[SEQ * DIM];
__device__ unsigned short g_m_hi[SEQ * MLPD],  g_m_lo[SEQ * MLPD];
__device__ unsigned short g_wp_hi[DIM * DIM],        g_wp_lo[DIM * DIM];
__device__ unsigned short g_qkvT_hi[12 * QKVD * DIM], g_qkvT_lo[12 * QKVD * DIM];
__device__ unsigned short g_projT_hi[12 * DIM * DIM], g_projT_lo[12 * DIM * DIM];
__device__ unsigned short g_fc1T_hi[12 * MLPD * DIM], g_fc1T_lo[12 * MLPD * DIM];
__device__ unsigned short g_fc2T_hi[12 * DIM * MLPD], g_fc2T_lo[12 * DIM * MLPD];

// ================= helpers =================
__device__ __forceinline__ uint32_t smem_u32(const void* p) {
    uint32_t a;
    asm("{ .reg .u64 t; cvta.to.shared.u64 t, %1; cvt.u32.u64 %0, t; }" : "=r"(a) : "l"(p));
    return a;
}
__device__ __forceinline__ void split1(float v, unsigned short& hi, unsigned short& lo) {
    __nv_bfloat16 h = __float2bfloat16(v);
    __nv_bfloat16 l = __float2bfloat16(v - __bfloat162float(h));
    hi = __bfloat16_as_ushort(h);
    lo = __bfloat16_as_ushort(l);
}

#define LDM4(r, addr) \
    asm volatile("ldmatrix.sync.aligned.m8n8.x4.shared.b16 {%0,%1,%2,%3}, [%4];" \
        : "=r"((r)[0]), "=r"((r)[1]), "=r"((r)[2]), "=r"((r)[3]) : "r"(addr))

#define MMA_BF16(c, a, b0, b1) \
    asm volatile("mma.sync.aligned.m16n8k16.row.col.f32.bf16.bf16.f32 " \
        "{%0,%1,%2,%3}, {%4,%5,%6,%7}, {%8,%9}, {%0,%1,%2,%3};" \
        : "+f"((c)[0]), "+f"((c)[1]), "+f"((c)[2]), "+f"((c)[3]) \
        : "r"((a)[0]), "r"((a)[1]), "r"((a)[2]), "r"((a)[3]), "r"(b0), "r"(b1))

#define CPA16(dst, src, sz) \
    asm volatile("cp.async.cg.shared.global [%0], [%1], 16, %2;" \
        :: "r"(dst), "l"(src), "r"(sz))
#define CPA_COMMIT() asm volatile("cp.async.commit_group;")
#define CPA_WAIT1()  asm volatile("cp.async.wait_group 1;")

// ---------------- transpose + split: fp32 [K,N] -> bf16 hi/lo [N,K] ----------------
__global__ void transpose_split_kernel(const float* __restrict__ in,
        unsigned short* __restrict__ ohi, unsigned short* __restrict__ olo, int K, int N) {
    __shared__ float t[32][33];
    size_t base = (size_t)blockIdx.z * K * N;
    int n0 = blockIdx.x * 32, k0 = blockIdx.y * 32;
    int tx = threadIdx.x, ty = threadIdx.y;
    #pragma unroll
    for (int j = 0; j < 32; j += 8)
        t[ty + j][tx] = in[base + (size_t)(k0 + ty + j) * N + n0 + tx];
    __syncthreads();
    #pragma unroll
    for (int j = 0; j < 32; j += 8) {
        unsigned short hi, lo;
        split1(t[tx][ty + j], hi, lo);
        size_t o = base + (size_t)(n0 + ty + j) * K + k0 + tx;
        ohi[o] = hi; olo[o] = lo;
    }
}

// ---------------- elementwise split ----------------
__global__ void split_kernel(const float* __restrict__ in,
        unsigned short* __restrict__ hi, unsigned short* __restrict__ lo, int n) {
    int i = blockIdx.x * blockDim.x + threadIdx.x;
    if (i >= n) return;
    split1(in[i], hi[i], lo[i]);
}

// ===================================================================================
// bf16x3 MMA GEMM (exact best configuration)
// ===================================================================================
constexpr int RS = 80;
constexpr int NSTG = 3;
constexpr int AL_OFF = 64 * RS;
constexpr int BH_OFF = 2 * 64 * RS;
constexpr int BL_OFF = BH_OFF + 128 * RS;
constexpr int STG    = BH_OFF + 2 * 128 * RS;   // 30720

__device__ __forceinline__ void load_stage(uint32_t sb,
        const unsigned short* __restrict__ Ahi, const unsigned short* __restrict__ Alo,
        const unsigned short* __restrict__ Bhi, const unsigned short* __restrict__ Blo,
        int row0, int col0, int K, int k0, int M, int tid) {
    int r = tid >> 2, ch = tid & 3;
    uint32_t doff = (uint32_t)(r * RS + ch * 16);
    size_t asrc = (size_t)(row0 + r) * K + k0 + ch * 8;
    int av = (row0 + r < M) ? 16 : 0;
    CPA16(sb + doff, Ahi + asrc, av);
    CPA16(sb + AL_OFF + doff, Alo + asrc, av);
    size_t b0 = (size_t)(col0 + r) * K + k0 + ch * 8;
    size_t b1 = (size_t)(col0 + 64 + r) * K + k0 + ch * 8;
    CPA16(sb + BH_OFF + doff, Bhi + b0, 16);
    CPA16(sb + BH_OFF + doff + 64 * RS, Bhi + b1, 16);
    CPA16(sb + BL_OFF + doff, Blo + b0, 16);
    CPA16(sb + BL_OFF + doff + 64 * RS, Blo + b1, 16);
    CPA_COMMIT();
}

__global__ void __launch_bounds__(256, 2) mma_gemm(
        const unsigned short* __restrict__ Ahi, const unsigned short* __restrict__ Alo,
        const unsigned short* __restrict__ Bhi, const unsigned short* __restrict__ Blo,
        const float* __restrict__ bias, const float* __restrict__ res,
        float* __restrict__ C, unsigned short* __restrict__ Chi,
        unsigned short* __restrict__ Clo,
        int M, int N, int K, int act) {
    extern __shared__ __align__(128) char sm[];
    const int tid = threadIdx.x;
    const int lane = tid & 31, wid = tid >> 5;
    const int wm = wid & 1, wn = wid >> 1;
    const int row0 = blockIdx.y * 64, col0 = blockIdx.x * 128;
    const uint32_t smb = smem_u32(sm);

    const int a_row = ((lane >> 3) & 1) * 8 + (lane & 7);
    const int a_kb  = (lane >> 4) * 16;
    const int b_row = (lane >> 4) * 8 + (lane & 7);
    const int b_kb  = ((lane >> 3) & 1) * 16;

    float c[2][4][4];
    #pragma unroll
    for (int i = 0; i < 2; i++)
        #pragma unroll
        for (int j = 0; j < 4; j++)
            #pragma unroll
            for (int k = 0; k < 4; k++) c[i][j][k] = 0.f;

    const int nk = K >> 5;
    load_stage(smb, Ahi, Alo, Bhi, Blo, row0, col0, K, 0, M, tid);
    load_stage(smb + STG, Ahi, Alo, Bhi, Blo, row0, col0, K, 32, M, tid);

    int buf = 0;
    for (int it = 0; it < nk; it++) {
        CPA_WAIT1();
        __syncthreads();
        if (it + 2 < nk) {
            int nb = buf + 2; if (nb >= NSTG) nb -= NSTG;
            load_stage(smb + (uint32_t)nb * STG, Ahi, Alo, Bhi, Blo,
                       row0, col0, K, (it + 2) << 5, M, tid);
        }
        uint32_t sb = smb + (uint32_t)buf * STG;
        #pragma unroll
        for (int kk = 0; kk < 2; kk++) {
            uint32_t bh[8], bl[8];
            #pragma unroll
            for (int nip = 0; nip < 2; nip++) {
                uint32_t baddr = sb + BH_OFF + (wn * 32 + nip * 16 + b_row) * RS + b_kb + kk * 32;
                LDM4(&bh[nip * 4], baddr);
                LDM4(&bl[nip * 4], baddr + (BL_OFF - BH_OFF));
            }
            #pragma unroll
            for (int mi = 0; mi < 2; mi++) {
                uint32_t ah[4], al[4];
                uint32_t aaddr = sb + (wm * 32 + mi * 16 + a_row) * RS + a_kb + kk * 32;
                LDM4(ah, aaddr);
                LDM4(al, aaddr + AL_OFF);
                #pragma unroll
                for (int ni = 0; ni < 4; ni++) {
                    uint32_t b0h = bh[(ni >> 1) * 4 + (ni & 1) * 2];
                    uint32_t b1h = bh[(ni >> 1) * 4 + (ni & 1) * 2 + 1];
                    uint32_t b0l = bl[(ni >> 1) * 4 + (ni & 1) * 2];
                    uint32_t b1l = bl[(ni >> 1) * 4 + (ni & 1) * 2 + 1];
                    MMA_BF16(c[mi][ni], ah, b0h, b1h);
                    MMA_BF16(c[mi][ni], ah, b0l, b1l);
                    MMA_BF16(c[mi][ni], al, b0h, b1h);
                }
            }
        }
        buf++; if (buf >= NSTG) buf = 0;
    }

    // ---- epilogue ----
    const int g = lane >> 2, t = lane & 3;
    #pragma unroll
    for (int mi = 0; mi < 2; mi++) {
        #pragma unroll
        for (int ni = 0; ni < 4; ni++) {
            int col = col0 + wn * 32 + ni * 8 + t * 2;
            float2 bb = bias ? *(const float2*)(bias + col) : make_float2(0.f, 0.f);
            #pragma unroll
            for (int half = 0; half < 2; half++) {
                int gm = row0 + wm * 32 + mi * 16 + g + half * 8;
                if (gm >= M) continue;
                float v0 = c[mi][ni][half * 2 + 0] + bb.x;
                float v1 = c[mi][ni][half * 2 + 1] + bb.y;
                if (act) {
                    v0 = 0.5f * v0 * (1.f + erff(v0 * 0.70710678118f));
                    v1 = 0.5f * v1 * (1.f + erff(v1 * 0.70710678118f));
                }
                if (res) {
                    float2 rv = *(const float2*)(res + (size_t)gm * N + col);
                    v0 += rv.x; v1 += rv.y;
                }
                size_t o = (size_t)gm * N + col;
                if (Chi) {
                    unsigned short h0, l0, h1, l1;
                    split1(v0, h0, l0);
                    split1(v1, h1, l1);
                    *(uint32_t*)(Chi + o) = (uint32_t)h0 | ((uint32_t)h1 << 16);
                    *(uint32_t*)(Clo + o) = (uint32_t)l0 | ((uint32_t)l1 << 16);
                } else {
                    *(float2*)(C + o) = make_float2(v0, v1);
                }
            }
        }
    }
}

// ---------------- patch extraction -> bf16 hi/lo ----------------
__global__ void patch_kernel(const float* __restrict__ x,
        unsigned short* __restrict__ Phi, unsigned short* __restrict__ Plo) {
    int idx = blockIdx.x * blockDim.x + threadIdx.x;
    if (idx >= 1568 * 768) return;
    int m = idx / 768, kcol = idx % 768;
    int t = m / 196, n = m % 196;
    int hp = n / 14, wp = n % 14;
    int c = kcol / 256, rem = kcol % 256;
    int ii = rem / 16, jj = rem % 16;
    float v = x[((t * 3 + c) * 224 + hp * 16 + ii) * 224 + wp * 16 + jj];
    split1(v, Phi[idx], Plo[idx]);
}

// ---------------- assemble h ----------------
__global__ void assemble_kernel(const float* __restrict__ emb, const float* __restrict__ cls,
                                const float* __restrict__ pos, float* __restrict__ h) {
    int idx = blockIdx.x * blockDim.x + threadIdx.x;
    if (idx >= SEQ * DIM) return;
    int m = idx / DIM, dd = idx % DIM;
    int t = m / NTOK, r = m % NTOK;
    float v;
    if (r == 0) {
        v = cls[dd] + pos[dd];
    } else {
        int pp = r - 1;
        int f = pp * DIM + dd;
        int n = f % NPAT, dc = f / NPAT;
        v = emb[(t * NPAT + n) * DIM + dc] + pos[(1 + pp) * DIM + dd];
    }
    h[idx] = v;
}

// ---------------- block reduction ----------------
__device__ __forceinline__ float block_sum256(float v, float* sh) {
    #pragma unroll
    for (int o = 16; o; o >>= 1) v += __shfl_xor_sync(0xffffffffu, v, o);
    if ((threadIdx.x & 31) == 0) sh[threadIdx.x >> 5] = v;
    __syncthreads();
    float t = 0.f;
    #pragma unroll
    for (int i = 0; i < 8; i++) t += sh[i];
    __syncthreads();
    return t;
}

// ---------------- LayerNorm -> bf16 hi/lo ----------------
__global__ void ln_split_kernel(const float* __restrict__ x, const float* __restrict__ g,
        const float* __restrict__ b, unsigned short* __restrict__ yhi,
        unsigned short* __restrict__ ylo) {
    __shared__ float sh[8];
    int row = blockIdx.x, tid = threadIdx.x;
    const float* xr = x + (size_t)row * DIM;
    float v0 = xr[tid], v1 = xr[tid + 256], v2 = xr[tid + 512];
    float mean = block_sum256(v0 + v1 + v2, sh) * (1.f / DIM);
    float d0 = v0 - mean, d1 = v1 - mean, d2 = v2 - mean;
    float var = block_sum256(d0 * d0 + d1 * d1 + d2 * d2, sh) * (1.f / DIM);
    float inv = rsqrtf(var + 1e-5f);
    size_t o = (size_t)row * DIM + tid;
    float y0 = d0 * inv * g[tid]       + b[tid];
    float y1 = d1 * inv * g[tid + 256] + b[tid + 256];
    float y2 = d2 * inv * g[tid + 512] + b[tid + 512];
    split1(y0, yhi[o],       ylo[o]);
    split1(y1, yhi[o + 256], ylo[o + 256]);
    split1(y2, yhi[o + 512], ylo[o + 512]);
}

// ---------------- final LayerNorm (fp32 out) ----------------
__global__ void ln_kernel(const float* __restrict__ x, const float* __restrict__ g,
                          const float* __restrict__ b, float* __restrict__ y) {
    __shared__ float sh[8];
    int row = blockIdx.x, tid = threadIdx.x;
    const float* xr = x + (size_t)row * DIM;
    float v0 = xr[tid], v1 = xr[tid + 256], v2 = xr[tid + 512];
    float mean = block_sum256(v0 + v1 + v2, sh) * (1.f / DIM);
    float d0 = v0 - mean, d1 = v1 - mean, d2 = v2 - mean;
    float var = block_sum256(d0 * d0 + d1 * d1 + d2 * d2, sh) * (1.f / DIM);
    float inv = rsqrtf(var + 1e-5f);
    float* yr = y + (size_t)row * DIM;
    yr[tid]       = d0 * inv * g[tid]       + b[tid];
    yr[tid + 256] = d1 * inv * g[tid + 256] + b[tid + 256];
    yr[tid + 512] = d2 * inv * g[tid + 512] + b[tid + 512];
}

// ---------------- attention, templated; fused v-mean for divided layers ----------
// AV phase: 2 keys/warp/iter (half-warps), float4 V loads, shfl-combined halves.
template <int QBT, int NTHR, int KCH, bool HASVM>
__global__ void __launch_bounds__(NTHR) attn_kernel(
        const float* __restrict__ qkv,
        unsigned short* __restrict__ ohi, unsigned short* __restrict__ olo,
        int keyLen, int keyLenP, int numSeg) {
    constexpr int NWARP = NTHR / 32;
    constexpr int NREP  = (QBT + NWARP - 1) / NWARP;
    extern __shared__ float smf[];
    float* qs   = smf;                        // QBT*HD
    float* sc   = smf + QBT * HD;             // QBT*keyLenP
    float* red  = sc + QBT * keyLenP;         // NWARP*QBT*HD
    float* vred = red + NWARP * QBT * HD;     // NWARP*HD (HASVM only)
    __shared__ float wsum[QBT];
    int tid = threadIdx.x;
    int hseg = blockIdx.y;
    int h = hseg / numSeg, seg = hseg % numSeg;
    int base = seg * keyLen;
    int q0 = blockIdx.x * QBT;
    int nq = min(QBT, keyLen - q0);

    for (int i = tid; i < QBT * HD; i += NTHR) {
        int qi = i / HD, d = i % HD;
        qs[i] = (qi < nq) ? qkv[(size_t)(base + q0 + qi) * QKVD + h * HD + d] : 0.f;
    }
    __syncthreads();

    // ---- scores: KCH keys per thread ----
    const int nkb = (keyLen + KCH - 1) / KCH;
    for (int kb = tid; kb < nkb; kb += NTHR) {
        int kk = kb * KCH;
        float acc[QBT][KCH];
        #pragma unroll
        for (int qi = 0; qi < QBT; qi++)
            #pragma unroll
            for (int c = 0; c < KCH; c++) acc[qi][c] = 0.f;
        const float* kbase0 = qkv + (size_t)(base + kk) * QKVD + DIM + h * HD;
        int voff[KCH];
        #pragma unroll
        for (int c = 0; c < KCH; c++) voff[c] = (kk + c < keyLen) ? c : 0;
        #pragma unroll 4
        for (int j = 0; j < 16; j++) {
            float4 kf[KCH];
            #pragma unroll
            for (int c = 0; c < KCH; c++)
                kf[c] = *(const float4*)(kbase0 + (size_t)voff[c] * QKVD + j * 4);
            #pragma unroll
            for (int qi = 0; qi < QBT; qi++) {
                float4 q = *(const float4*)(qs + qi * HD + j * 4);
                #pragma unroll
                for (int c = 0; c < KCH; c++)
                    acc[qi][c] += q.x * kf[c].x + q.y * kf[c].y
                                + q.z * kf[c].z + q.w * kf[c].w;
            }
        }
        #pragma unroll
        for (int qi = 0; qi < QBT; qi++) {
            float* dst = sc + qi * keyLenP + kk;
            if (kk + KCH <= keyLen) {
                #pragma unroll
                for (int c = 0; c < KCH; c++) dst[c] = acc[qi][c] * ASCALE;
            } else {
                for (int c = 0; c < KCH; c++)
                    if (kk + c < keyLen) dst[c] = acc[qi][c] * ASCALE;
            }
        }
    }
    __syncthreads();

    // ---- softmax: warp w handles queries w, w+NWARP, ... ----
    int w = tid >> 5, lane = tid & 31;
    #pragma unroll
    for (int rep = 0; rep < NREP; rep++) {
        int q = w + rep * NWARP;
        if (q < nq) {
            float mx = -1e30f;
            for (int kk = lane; kk < keyLen; kk += 32) mx = fmaxf(mx, sc[q * keyLenP + kk]);
            #pragma unroll
            for (int off = 16; off; off >>= 1) mx = fmaxf(mx, __shfl_xor_sync(0xffffffffu, mx, off));
            float sum = 0.f;
            for (int kk = lane; kk < keyLen; kk += 32) {
                float e = __expf(sc[q * keyLenP + kk] - mx);
                sc[q * keyLenP + kk] = e;
                sum += e;
            }
            #pragma unroll
            for (int off = 16; off; off >>= 1) sum += __shfl_xor_sync(0xffffffffu, sum, off);
            if (lane == 0) wsum[q] = sum;
        }
    }
    __syncthreads();

    // ---- AV: 2 keys per warp per iter, float4 V, half-warps combined by shfl ----
    {
        int lane16 = lane & 15;
        int keyOff = lane >> 4;
        int part = w;
        float4 acc[QBT];
        #pragma unroll
        for (int qi = 0; qi < QBT; qi++) acc[qi] = make_float4(0.f, 0.f, 0.f, 0.f);
        float4 vsum = make_float4(0.f, 0.f, 0.f, 0.f);
        const float* vbase = qkv + 2 * DIM + h * HD + lane16 * 4;
        for (int kk = part * 2 + keyOff; kk < keyLen; kk += 2 * NWARP) {
            float4 v = *(const float4*)(vbase + (size_t)(base + kk) * QKVD);
            if (HASVM) { vsum.x += v.x; vsum.y += v.y; vsum.z += v.z; vsum.w += v.w; }
            #pragma unroll
            for (int qi = 0; qi < QBT; qi++) {
                float p = sc[qi * keyLenP + kk];
                acc[qi].x += p * v.x; acc[qi].y += p * v.y;
                acc[qi].z += p * v.z; acc[qi].w += p * v.w;
            }
        }
        // combine the two half-warp key streams (same dims on lane l and l^16)
        #pragma unroll
        for (int qi = 0; qi < QBT; qi++) {
            acc[qi].x += __shfl_xor_sync(0xffffffffu, acc[qi].x, 16);
            acc[qi].y += __shfl_xor_sync(0xffffffffu, acc[qi].y, 16);
            acc[qi].z += __shfl_xor_sync(0xffffffffu, acc[qi].z, 16);
            acc[qi].w += __shfl_xor_sync(0xffffffffu, acc[qi].w, 16);
        }
        if (HASVM) {
            vsum.x += __shfl_xor_sync(0xffffffffu, vsum.x, 16);
            vsum.y += __shfl_xor_sync(0xffffffffu, vsum.y, 16);
            vsum.z += __shfl_xor_sync(0xffffffffu, vsum.z, 16);
            vsum.w += __shfl_xor_sync(0xffffffffu, vsum.w, 16);
        }
        if (keyOff == 0) {
            #pragma unroll
            for (int qi = 0; qi < QBT; qi++)
                *(float4*)(red + (part * QBT + qi) * HD + lane16 * 4) = acc[qi];
            if (HASVM)
                *(float4*)(vred + part * HD + lane16 * 4) = vsum;
        }
        __syncthreads();
        float invLen = 1.f / (float)keyLen;
        #pragma unroll
        for (int rep = 0; rep < NREP; rep++) {
            int qi = w + rep * NWARP;
            if (qi < nq) {
                int d2 = lane;
                float sx = 0.f, sy = 0.f;
                #pragma unroll
                for (int pp = 0; pp < NWARP; pp++) {
                    float2 r = *(const float2*)(red + (pp * QBT + qi) * HD + d2 * 2);
                    sx += r.x; sy += r.y;
                }
                float invw = 1.f / wsum[qi];
                sx *= invw; sy *= invw;
                if (HASVM) {
                    float vx = 0.f, vy = 0.f;
                    #pragma unroll
                    for (int pp = 0; pp < NWARP; pp++) {
                        float2 r = *(const float2*)(vred + pp * HD + d2 * 2);
                        vx += r.x; vy += r.y;
                    }
                    sx += vx * invLen; sy += vy * invLen;
                }
                size_t o = (size_t)(base + q0 + qi) * DIM + h * HD + d2 * 2;
                split1(sx, ohi[o],     olo[o]);
                split1(sy, ohi[o + 1], olo[o + 1]);
            }
        }
    }
}

// ---------------- host ----------------
static void run_mma(const unsigned short* Ahi, const unsigned short* Alo,
                    const unsigned short* Bhi, const unsigned short* Blo,
                    const float* bias, const float* res, float* C,
                    unsigned short* Chi, unsigned short* Clo,
                    int M, int N, int K, int act) {
    dim3 grid(N / 128, (M + 63) / 64);
    mma_gemm<<<grid, 256, NSTG * STG>>>(Ahi, Alo, Bhi, Blo, bias, res, C, Chi, Clo, M, N, K, act);
}

extern "C" void kernel_launch(void* const* d_in, const int* in_sizes, int n_in,
                              void* d_out, int out_size) {
    const float* x       = (const float*)d_in[0];
    const float* W_patch = (const float*)d_in[1];
    const float* b_patch = (const float*)d_in[2];
    const float* cls     = (const float*)d_in[3];
    const float* pos     = (const float*)d_in[4];
    const float* ln1_g   = (const float*)d_in[5];
    const float* ln1_b   = (const float*)d_in[6];
    const float* qkv_w   = (const float*)d_in[7];
    const float* qkv_b   = (const float*)d_in[8];
    const float* proj_w  = (const float*)d_in[9];
    const float* proj_b  = (const float*)d_in[10];
    const float* ln2_g   = (const float*)d_in[11];
    const float* ln2_b   = (const float*)d_in[12];
    const float* fc1_w   = (const float*)d_in[13];
    const float* fc1_b   = (const float*)d_in[14];
    const float* fc2_w   = (const float*)d_in[15];
    const float* fc2_b   = (const float*)d_in[16];
    const float* lnf_g   = (const float*)d_in[17];
    const float* lnf_b   = (const float*)d_in[18];

    float *emb_, *h_, *qkv_;
    unsigned short *pH, *pL, *aH, *aL, *oH, *oL, *mH, *mL;
    unsigned short *wpH, *wpL, *qkH, *qkL, *prH, *prL, *f1H, *f1L, *f2H, *f2L;
    cudaGetSymbolAddress((void**)&emb_, g_emb);
    cudaGetSymbolAddress((void**)&h_,   g_h);
    cudaGetSymbolAddress((void**)&qkv_, g_qkv);
    cudaGetSymbolAddress((void**)&pH, g_p_hi);   cudaGetSymbolAddress((void**)&pL, g_p_lo);
    cudaGetSymbolAddress((void**)&aH, g_a_hi);   cudaGetSymbolAddress((void**)&aL, g_a_lo);
    cudaGetSymbolAddress((void**)&oH, g_o_hi);   cudaGetSymbolAddress((void**)&oL, g_o_lo);
    cudaGetSymbolAddress((void**)&mH, g_m_hi);   cudaGetSymbolAddress((void**)&mL, g_m_lo);
    cudaGetSymbolAddress((void**)&wpH, g_wp_hi); cudaGetSymbolAddress((void**)&wpL, g_wp_lo);
    cudaGetSymbolAddress((void**)&qkH, g_qkvT_hi); cudaGetSymbolAddress((void**)&qkL, g_qkvT_lo);
    cudaGetSymbolAddress((void**)&prH, g_projT_hi); cudaGetSymbolAddress((void**)&prL, g_projT_lo);
    cudaGetSymbolAddress((void**)&f1H, g_fc1T_hi); cudaGetSymbolAddress((void**)&f1L, g_fc1T_lo);
    cudaGetSymbolAddress((void**)&f2H, g_fc2T_hi); cudaGetSymbolAddress((void**)&f2L, g_fc2T_lo);

    cudaFuncSetAttribute(mma_gemm, cudaFuncAttributeMaxDynamicSharedMemorySize, NSTG * STG);

    // spatial: QBT=8, 256 thr, KCH=4, HASVM; keyLen=197 (pad 200)
    size_t smem_sp = (size_t)(8 * HD + 8 * 200 + 8 * 8 * HD + 8 * HD) * sizeof(float);
    // joint: QBT=16, 512 thr, KCH=2, no VM; keyLen=SEQ
    size_t smem_joint = (size_t)(16 * HD + 16 * SEQ + 16 * 16 * HD) * sizeof(float);
    cudaFuncSetAttribute((const void*)attn_kernel<16, 512, 2, false>,
                         cudaFuncAttributeMaxDynamicSharedMemorySize, (int)smem_joint);
    cudaFuncSetAttribute((const void*)attn_kernel<8, 256, 4, true>,
                         cudaFuncAttributeMaxDynamicSharedMemorySize, (int)smem_sp);

    patch_kernel<<<(1568 * 768 + 255) / 256, 256>>>(x, pH, pL);                       // 0
    split_kernel<<<(DIM * DIM + 255) / 256, 256>>>(W_patch, wpH, wpL, DIM * DIM);     // 1
    dim3 tb(32, 8);
    transpose_split_kernel<<<dim3(QKVD / 32, DIM / 32, 12), tb>>>(qkv_w, qkH, qkL, DIM, QKVD); // 2
    run_mma(pH, pL, wpH, wpL, b_patch, nullptr, emb_, nullptr, nullptr, 1568, 768, 768, 0);    // 3 <- profiled
    transpose_split_kernel<<<dim3(DIM / 32,  DIM / 32, 12), tb>>>(proj_w, prH, prL, DIM, DIM);
    transpose_split_kernel<<<dim3(MLPD / 32, DIM / 32, 12), tb>>>(fc1_w,  f1H, f1L, DIM, MLPD);
    transpose_split_kernel<<<dim3(DIM / 32, MLPD / 32, 12), tb>>>(fc2_w,  f2H, f2L, MLPD, DIM);
    assemble_kernel<<<(SEQ * DIM + 255) / 256, 256>>>(emb_, cls, pos, h_);

    for (int i = 0; i < 12; i++) {
        ln_split_kernel<<<SEQ, 256>>>(h_, ln1_g + i * DIM, ln1_b + i * DIM, aH, aL);
        run_mma(aH, aL, qkH + (size_t)i * QKVD * DIM, qkL + (size_t)i * QKVD * DIM,
                qkv_b + i * QKVD, nullptr, qkv_, nullptr, nullptr, SEQ, QKVD, DIM, 0);
        if ((i & 1) == 0) {
            dim3 g((NTOK + 7) / 8, NHEAD * TFR);
            attn_kernel<8, 256, 4, true><<<g, 256, smem_sp>>>(qkv_, oH, oL, NTOK, 200, TFR);
        } else {
            dim3 g((SEQ + 15) / 16, NHEAD);
            attn_kernel<16, 512, 2, false><<<g, 512, smem_joint>>>(qkv_, oH, oL, SEQ, SEQ, 1);
        }
        run_mma(oH, oL, prH + (size_t)i * DIM * DIM, prL + (size_t)i * DIM * DIM,
                proj_b + i * DIM, h_, h_, nullptr, nullptr, SEQ, DIM, DIM, 0);
        ln_split_kernel<<<SEQ, 256>>>(h_, ln2_g + i * DIM, ln2_b + i * DIM, aH, aL);
        run_mma(aH, aL, f1H + (size_t)i * MLPD * DIM, f1L + (size_t)i * MLPD * DIM,
                fc1_b + i * MLPD, nullptr, nullptr, mH, mL, SEQ, MLPD, DIM, 1);
        run_mma(mH, mL, f2H + (size_t)i * DIM * MLPD, f2L + (size_t)i * DIM * MLPD,
                fc2_b + i * DIM, h_, h_, nullptr, nullptr, SEQ, DIM, MLPD, 0);
    }

    ln_kernel<<<SEQ, 256>>>(h_, lnf_g, lnf_b, (float*)d_out);
}

// round 16
// speedup vs baseline: 1.0640x; 1.0329x over previous
#include <cuda_runtime.h>
#include <cuda_bf16.h>
#include <math.h>
#include <stdint.h>

constexpr int SEQ  = 1576;   // T*N tokens
constexpr int DIM  = 768;
constexpr int NHEAD = 12;
constexpr int HD   = 64;
constexpr int TFR  = 8;      // frames
constexpr int NTOK = 197;    // tokens per frame
constexpr int NPAT = 196;
constexpr int MLPD = 3072;
constexpr int QKVD = 2304;
constexpr float ASCALE = 0.125f;

// ---------------- scratch (no allocation allowed) ----------------
__device__ float g_emb[1568 * 768];
__device__ float g_h[SEQ * DIM];
__device__ float g_qkv[SEQ * QKVD];
__device__ unsigned short g_p_hi[1568 * 768],  g_p_lo[1568 * 768];
__device__ unsigned short g_a_hi[SEQ * DIM],   g_a_lo[SEQ * DIM];
__device__ unsigned short g_o_hi[SEQ * DIM],   g_o_lo[SEQ * DIM];
__device__ unsigned short g_m_hi[SEQ * MLPD],  g_m_lo[SEQ * MLPD];
__device__ unsigned short g_wp_hi[DIM * DIM],        g_wp_lo[DIM * DIM];
__device__ unsigned short g_qkvT_hi[12 * QKVD * DIM], g_qkvT_lo[12 * QKVD * DIM];
__device__ unsigned short g_projT_hi[12 * DIM * DIM], g_projT_lo[12 * DIM * DIM];
__device__ unsigned short g_fc1T_hi[12 * MLPD * DIM], g_fc1T_lo[12 * MLPD * DIM];
__device__ unsigned short g_fc2T_hi[12 * DIM * MLPD], g_fc2T_lo[12 * DIM * MLPD];

// ================= helpers =================
__device__ __forceinline__ uint32_t smem_u32(const void* p) {
    uint32_t a;
    asm("{ .reg .u64 t; cvta.to.shared.u64 t, %1; cvt.u32.u64 %0, t; }" : "=r"(a) : "l"(p));
    return a;
}
__device__ __forceinline__ void split1(float v, unsigned short& hi, unsigned short& lo) {
    __nv_bfloat16 h = __float2bfloat16(v);
    __nv_bfloat16 l = __float2bfloat16(v - __bfloat162float(h));
    hi = __bfloat16_as_ushort(h);
    lo = __bfloat16_as_ushort(l);
}

#define LDM4(r, addr) \
    asm volatile("ldmatrix.sync.aligned.m8n8.x4.shared.b16 {%0,%1,%2,%3}, [%4];" \
        : "=r"((r)[0]), "=r"((r)[1]), "=r"((r)[2]), "=r"((r)[3]) : "r"(addr))

#define MMA_BF16(c, a, b0, b1) \
    asm volatile("mma.sync.aligned.m16n8k16.row.col.f32.bf16.bf16.f32 " \
        "{%0,%1,%2,%3}, {%4,%5,%6,%7}, {%8,%9}, {%0,%1,%2,%3};" \
        : "+f"((c)[0]), "+f"((c)[1]), "+f"((c)[2]), "+f"((c)[3]) \
        : "r"((a)[0]), "r"((a)[1]), "r"((a)[2]), "r"((a)[3]), "r"(b0), "r"(b1))

#define CPA16(dst, src, sz) \
    asm volatile("cp.async.cg.shared.global [%0], [%1], 16, %2;" \
        :: "r"(dst), "l"(src), "r"(sz))
#define CPA_COMMIT() asm volatile("cp.async.commit_group;")
#define CPA_WAIT1()  asm volatile("cp.async.wait_group 1;")

// ---------------- transpose + split: fp32 [K,N] -> bf16 hi/lo [N,K] ----------------
__global__ void transpose_split_kernel(const float* __restrict__ in,
        unsigned short* __restrict__ ohi, unsigned short* __restrict__ olo, int K, int N) {
    __shared__ float t[32][33];
    size_t base = (size_t)blockIdx.z * K * N;
    int n0 = blockIdx.x * 32, k0 = blockIdx.y * 32;
    int tx = threadIdx.x, ty = threadIdx.y;
    #pragma unroll
    for (int j = 0; j < 32; j += 8)
        t[ty + j][tx] = in[base + (size_t)(k0 + ty + j) * N + n0 + tx];
    __syncthreads();
    #pragma unroll
    for (int j = 0; j < 32; j += 8) {
        unsigned short hi, lo;
        split1(t[tx][ty + j], hi, lo);
        size_t o = base + (size_t)(n0 + ty + j) * K + k0 + tx;
        ohi[o] = hi; olo[o] = lo;
    }
}

// ---------------- elementwise split ----------------
__global__ void split_kernel(const float* __restrict__ in,
        unsigned short* __restrict__ hi, unsigned short* __restrict__ lo, int n) {
    int i = blockIdx.x * blockDim.x + threadIdx.x;
    if (i >= n) return;
    split1(in[i], hi[i], lo[i]);
}

// ===================================================================================
// bf16x3 MMA GEMM. SK=false: full epilogue (bias/GELU/res/split-out).
// SK=true: split-K over blockIdx.z, epilogue = fp32 atomicAdd into C (which already
//          holds the residual); bias added by the z==0 slice.
// ===================================================================================
constexpr int RS = 80;
constexpr int NSTG = 3;
constexpr int AL_OFF = 64 * RS;
constexpr int BH_OFF = 2 * 64 * RS;
constexpr int BL_OFF = BH_OFF + 128 * RS;
constexpr int STG    = BH_OFF + 2 * 128 * RS;   // 30720

__device__ __forceinline__ void load_stage(uint32_t sb,
        const unsigned short* __restrict__ Ahi, const unsigned short* __restrict__ Alo,
        const unsigned short* __restrict__ Bhi, const unsigned short* __restrict__ Blo,
        int row0, int col0, int K, int k0, int M, int tid) {
    int r = tid >> 2, ch = tid & 3;
    uint32_t doff = (uint32_t)(r * RS + ch * 16);
    size_t asrc = (size_t)(row0 + r) * K + k0 + ch * 8;
    int av = (row0 + r < M) ? 16 : 0;
    CPA16(sb + doff, Ahi + asrc, av);
    CPA16(sb + AL_OFF + doff, Alo + asrc, av);
    size_t b0 = (size_t)(col0 + r) * K + k0 + ch * 8;
    size_t b1 = (size_t)(col0 + 64 + r) * K + k0 + ch * 8;
    CPA16(sb + BH_OFF + doff, Bhi + b0, 16);
    CPA16(sb + BH_OFF + doff + 64 * RS, Bhi + b1, 16);
    CPA16(sb + BL_OFF + doff, Blo + b0, 16);
    CPA16(sb + BL_OFF + doff + 64 * RS, Blo + b1, 16);
    CPA_COMMIT();
}

template <bool SK>
__global__ void __launch_bounds__(256, 2) mma_gemm(
        const unsigned short* __restrict__ Ahi, const unsigned short* __restrict__ Alo,
        const unsigned short* __restrict__ Bhi, const unsigned short* __restrict__ Blo,
        const float* __restrict__ bias, const float* __restrict__ res,
        float* __restrict__ C, unsigned short* __restrict__ Chi,
        unsigned short* __restrict__ Clo,
        int M, int N, int K, int act) {
    extern __shared__ __align__(128) char sm[];
    const int tid = threadIdx.x;
    const int lane = tid & 31, wid = tid >> 5;
    const int wm = wid & 1, wn = wid >> 1;
    const int row0 = blockIdx.y * 64, col0 = blockIdx.x * 128;
    const uint32_t smb = smem_u32(sm);

    const int a_row = ((lane >> 3) & 1) * 8 + (lane & 7);
    const int a_kb  = (lane >> 4) * 16;
    const int b_row = (lane >> 4) * 8 + (lane & 7);
    const int b_kb  = ((lane >> 3) & 1) * 16;

    float c[2][4][4];
    #pragma unroll
    for (int i = 0; i < 2; i++)
        #pragma unroll
        for (int j = 0; j < 4; j++)
            #pragma unroll
            for (int k = 0; k < 4; k++) c[i][j][k] = 0.f;

    const int klen  = SK ? (K / gridDim.z) : K;
    const int kbase = SK ? blockIdx.z * klen : 0;
    const int nk = klen >> 5;
    load_stage(smb, Ahi, Alo, Bhi, Blo, row0, col0, K, kbase, M, tid);
    load_stage(smb + STG, Ahi, Alo, Bhi, Blo, row0, col0, K, kbase + 32, M, tid);

    int buf = 0;
    for (int it = 0; it < nk; it++) {
        CPA_WAIT1();
        __syncthreads();
        if (it + 2 < nk) {
            int nb = buf + 2; if (nb >= NSTG) nb -= NSTG;
            load_stage(smb + (uint32_t)nb * STG, Ahi, Alo, Bhi, Blo,
                       row0, col0, K, kbase + ((it + 2) << 5), M, tid);
        }
        uint32_t sb = smb + (uint32_t)buf * STG;
        #pragma unroll
        for (int kk = 0; kk < 2; kk++) {
            uint32_t bh[8], bl[8];
            #pragma unroll
            for (int nip = 0; nip < 2; nip++) {
                uint32_t baddr = sb + BH_OFF + (wn * 32 + nip * 16 + b_row) * RS + b_kb + kk * 32;
                LDM4(&bh[nip * 4], baddr);
                LDM4(&bl[nip * 4], baddr + (BL_OFF - BH_OFF));
            }
            #pragma unroll
            for (int mi = 0; mi < 2; mi++) {
                uint32_t ah[4], al[4];
                uint32_t aaddr = sb + (wm * 32 + mi * 16 + a_row) * RS + a_kb + kk * 32;
                LDM4(ah, aaddr);
                LDM4(al, aaddr + AL_OFF);
                #pragma unroll
                for (int ni = 0; ni < 4; ni++) {
                    uint32_t b0h = bh[(ni >> 1) * 4 + (ni & 1) * 2];
                    uint32_t b1h = bh[(ni >> 1) * 4 + (ni & 1) * 2 + 1];
                    uint32_t b0l = bl[(ni >> 1) * 4 + (ni & 1) * 2];
                    uint32_t b1l = bl[(ni >> 1) * 4 + (ni & 1) * 2 + 1];
                    MMA_BF16(c[mi][ni], ah, b0h, b1h);
                    MMA_BF16(c[mi][ni], ah, b0l, b1l);
                    MMA_BF16(c[mi][ni], al, b0h, b1h);
                }
            }
        }
        buf++; if (buf >= NSTG) buf = 0;
    }

    // ---- epilogue ----
    const int g = lane >> 2, t = lane & 3;
    #pragma unroll
    for (int mi = 0; mi < 2; mi++) {
        #pragma unroll
        for (int ni = 0; ni < 4; ni++) {
            int col = col0 + wn * 32 + ni * 8 + t * 2;
            float2 bb = (bias && (!SK || blockIdx.z == 0))
                        ? *(const float2*)(bias + col) : make_float2(0.f, 0.f);
            #pragma unroll
            for (int half = 0; half < 2; half++) {
                int gm = row0 + wm * 32 + mi * 16 + g + half * 8;
                if (gm >= M) continue;
                float v0 = c[mi][ni][half * 2 + 0] + bb.x;
                float v1 = c[mi][ni][half * 2 + 1] + bb.y;
                size_t o = (size_t)gm * N + col;
                if (SK) {
                    atomicAdd(C + o, v0);
                    atomicAdd(C + o + 1, v1);
                } else {
                    if (act) {
                        v0 = 0.5f * v0 * (1.f + erff(v0 * 0.70710678118f));
                        v1 = 0.5f * v1 * (1.f + erff(v1 * 0.70710678118f));
                    }
                    if (res) {
                        float2 rv = *(const float2*)(res + o);
                        v0 += rv.x; v1 += rv.y;
                    }
                    if (Chi) {
                        unsigned short h0, l0, h1, l1;
                        split1(v0, h0, l0);
                        split1(v1, h1, l1);
                        *(uint32_t*)(Chi + o) = (uint32_t)h0 | ((uint32_t)h1 << 16);
                        *(uint32_t*)(Clo + o) = (uint32_t)l0 | ((uint32_t)l1 << 16);
                    } else {
                        *(float2*)(C + o) = make_float2(v0, v1);
                    }
                }
            }
        }
    }
}

// ---------------- patch extraction -> bf16 hi/lo ----------------
__global__ void patch_kernel(const float* __restrict__ x,
        unsigned short* __restrict__ Phi, unsigned short* __restrict__ Plo) {
    int idx = blockIdx.x * blockDim.x + threadIdx.x;
    if (idx >= 1568 * 768) return;
    int m = idx / 768, kcol = idx % 768;
    int t = m / 196, n = m % 196;
    int hp = n / 14, wp = n % 14;
    int c = kcol / 256, rem = kcol % 256;
    int ii = rem / 16, jj = rem % 16;
    float v = x[((t * 3 + c) * 224 + hp * 16 + ii) * 224 + wp * 16 + jj];
    split1(v, Phi[idx], Plo[idx]);
}

// ---------------- assemble h ----------------
__global__ void assemble_kernel(const float* __restrict__ emb, const float* __restrict__ cls,
                                const float* __restrict__ pos, float* __restrict__ h) {
    int idx = blockIdx.x * blockDim.x + threadIdx.x;
    if (idx >= SEQ * DIM) return;
    int m = idx / DIM, dd = idx % DIM;
    int t = m / NTOK, r = m % NTOK;
    float v;
    if (r == 0) {
        v = cls[dd] + pos[dd];
    } else {
        int pp = r - 1;
        int f = pp * DIM + dd;
        int n = f % NPAT, dc = f / NPAT;
        v = emb[(t * NPAT + n) * DIM + dc] + pos[(1 + pp) * DIM + dd];
    }
    h[idx] = v;
}

// ---------------- block reduction ----------------
__device__ __forceinline__ float block_sum256(float v, float* sh) {
    #pragma unroll
    for (int o = 16; o; o >>= 1) v += __shfl_xor_sync(0xffffffffu, v, o);
    if ((threadIdx.x & 31) == 0) sh[threadIdx.x >> 5] = v;
    __syncthreads();
    float t = 0.f;
    #pragma unroll
    for (int i = 0; i < 8; i++) t += sh[i];
    __syncthreads();
    return t;
}

// ---------------- LayerNorm -> bf16 hi/lo ----------------
__global__ void ln_split_kernel(const float* __restrict__ x, const float* __restrict__ g,
        const float* __restrict__ b, unsigned short* __restrict__ yhi,
        unsigned short* __restrict__ ylo) {
    __shared__ float sh[8];
    int row = blockIdx.x, tid = threadIdx.x;
    const float* xr = x + (size_t)row * DIM;
    float v0 = xr[tid], v1 = xr[tid + 256], v2 = xr[tid + 512];
    float mean = block_sum256(v0 + v1 + v2, sh) * (1.f / DIM);
    float d0 = v0 - mean, d1 = v1 - mean, d2 = v2 - mean;
    float var = block_sum256(d0 * d0 + d1 * d1 + d2 * d2, sh) * (1.f / DIM);
    float inv = rsqrtf(var + 1e-5f);
    size_t o = (size_t)row * DIM + tid;
    float y0 = d0 * inv * g[tid]       + b[tid];
    float y1 = d1 * inv * g[tid + 256] + b[tid + 256];
    float y2 = d2 * inv * g[tid + 512] + b[tid + 512];
    split1(y0, yhi[o],       ylo[o]);
    split1(y1, yhi[o + 256], ylo[o + 256]);
    split1(y2, yhi[o + 512], ylo[o + 512]);
}

// ---------------- final LayerNorm (fp32 out) ----------------
__global__ void ln_kernel(const float* __restrict__ x, const float* __restrict__ g,
                          const float* __restrict__ b, float* __restrict__ y) {
    __shared__ float sh[8];
    int row = blockIdx.x, tid = threadIdx.x;
    const float* xr = x + (size_t)row * DIM;
    float v0 = xr[tid], v1 = xr[tid + 256], v2 = xr[tid + 512];
    float mean = block_sum256(v0 + v1 + v2, sh) * (1.f / DIM);
    float d0 = v0 - mean, d1 = v1 - mean, d2 = v2 - mean;
    float var = block_sum256(d0 * d0 + d1 * d1 + d2 * d2, sh) * (1.f / DIM);
    float inv = rsqrtf(var + 1e-5f);
    float* yr = y + (size_t)row * DIM;
    yr[tid]       = d0 * inv * g[tid]       + b[tid];
    yr[tid + 256] = d1 * inv * g[tid + 256] + b[tid + 256];
    yr[tid + 512] = d2 * inv * g[tid + 512] + b[tid + 512];
}

// ---------------- attention, templated; fused v-mean for divided layers ----------
template <int QBT, int NTHR, int KCH, bool HASVM>
__global__ void __launch_bounds__(NTHR) attn_kernel(
        const float* __restrict__ qkv,
        unsigned short* __restrict__ ohi, unsigned short* __restrict__ olo,
        int keyLen, int keyLenP, int numSeg) {
    constexpr int NWARP = NTHR / 32;
    constexpr int NREP  = (QBT + NWARP - 1) / NWARP;
    extern __shared__ float smf[];
    float* qs   = smf;                        // QBT*HD
    float* sc   = smf + QBT * HD;             // QBT*keyLenP
    float* red  = sc + QBT * keyLenP;         // NWARP*QBT*HD
    float* vred = red + NWARP * QBT * HD;     // NWARP*HD (HASVM only)
    __shared__ float wsum[QBT];
    int tid = threadIdx.x;
    int hseg = blockIdx.y;
    int h = hseg / numSeg, seg = hseg % numSeg;
    int base = seg * keyLen;
    int q0 = blockIdx.x * QBT;
    int nq = min(QBT, keyLen - q0);

    for (int i = tid; i < QBT * HD; i += NTHR) {
        int qi = i / HD, d = i % HD;
        qs[i] = (qi < nq) ? qkv[(size_t)(base + q0 + qi) * QKVD + h * HD + d] : 0.f;
    }
    __syncthreads();

    // ---- scores: KCH keys per thread ----
    const int nkb = (keyLen + KCH - 1) / KCH;
    for (int kb = tid; kb < nkb; kb += NTHR) {
        int kk = kb * KCH;
        float acc[QBT][KCH];
        #pragma unroll
        for (int qi = 0; qi < QBT; qi++)
            #pragma unroll
            for (int c = 0; c < KCH; c++) acc[qi][c] = 0.f;
        const float* kbase0 = qkv + (size_t)(base + kk) * QKVD + DIM + h * HD;
        int voff[KCH];
        #pragma unroll
        for (int c = 0; c < KCH; c++) voff[c] = (kk + c < keyLen) ? c : 0;
        #pragma unroll 4
        for (int j = 0; j < 16; j++) {
            float4 kf[KCH];
            #pragma unroll
            for (int c = 0; c < KCH; c++)
                kf[c] = *(const float4*)(kbase0 + (size_t)voff[c] * QKVD + j * 4);
            #pragma unroll
            for (int qi = 0; qi < QBT; qi++) {
                float4 q = *(const float4*)(qs + qi * HD + j * 4);
                #pragma unroll
                for (int c = 0; c < KCH; c++)
                    acc[qi][c] += q.x * kf[c].x + q.y * kf[c].y
                                + q.z * kf[c].z + q.w * kf[c].w;
            }
        }
        #pragma unroll
        for (int qi = 0; qi < QBT; qi++) {
            float* dst = sc + qi * keyLenP + kk;
            if (kk + KCH <= keyLen) {
                #pragma unroll
                for (int c = 0; c < KCH; c++) dst[c] = acc[qi][c] * ASCALE;
            } else {
                for (int c = 0; c < KCH; c++)
                    if (kk + c < keyLen) dst[c] = acc[qi][c] * ASCALE;
            }
        }
    }
    __syncthreads();

    // ---- softmax ----
    int w = tid >> 5, lane = tid & 31;
    #pragma unroll
    for (int rep = 0; rep < NREP; rep++) {
        int q = w + rep * NWARP;
        if (q < nq) {
            float mx = -1e30f;
            for (int kk = lane; kk < keyLen; kk += 32) mx = fmaxf(mx, sc[q * keyLenP + kk]);
            #pragma unroll
            for (int off = 16; off; off >>= 1) mx = fmaxf(mx, __shfl_xor_sync(0xffffffffu, mx, off));
            float sum = 0.f;
            for (int kk = lane; kk < keyLen; kk += 32) {
                float e = __expf(sc[q * keyLenP + kk] - mx);
                sc[q * keyLenP + kk] = e;
                sum += e;
            }
            #pragma unroll
            for (int off = 16; off; off >>= 1) sum += __shfl_xor_sync(0xffffffffu, sum, off);
            if (lane == 0) wsum[q] = sum;
        }
    }
    __syncthreads();

    // ---- AV: 2 keys per warp per iter, float4 V, half-warps combined by shfl ----
    {
        int lane16 = lane & 15;
        int keyOff = lane >> 4;
        int part = w;
        float4 acc[QBT];
        #pragma unroll
        for (int qi = 0; qi < QBT; qi++) acc[qi] = make_float4(0.f, 0.f, 0.f, 0.f);
        float4 vsum = make_float4(0.f, 0.f, 0.f, 0.f);
        const float* vbase = qkv + 2 * DIM + h * HD + lane16 * 4;
        for (int kk = part * 2 + keyOff; kk < keyLen; kk += 2 * NWARP) {
            float4 v = *(const float4*)(vbase + (size_t)(base + kk) * QKVD);
            if (HASVM) { vsum.x += v.x; vsum.y += v.y; vsum.z += v.z; vsum.w += v.w; }
            #pragma unroll
            for (int qi = 0; qi < QBT; qi++) {
                float p = sc[qi * keyLenP + kk];
                acc[qi].x += p * v.x; acc[qi].y += p * v.y;
                acc[qi].z += p * v.z; acc[qi].w += p * v.w;
            }
        }
        #pragma unroll
        for (int qi = 0; qi < QBT; qi++) {
            acc[qi].x += __shfl_xor_sync(0xffffffffu, acc[qi].x, 16);
            acc[qi].y += __shfl_xor_sync(0xffffffffu, acc[qi].y, 16);
            acc[qi].z += __shfl_xor_sync(0xffffffffu, acc[qi].z, 16);
            acc[qi].w += __shfl_xor_sync(0xffffffffu, acc[qi].w, 16);
        }
        if (HASVM) {
            vsum.x += __shfl_xor_sync(0xffffffffu, vsum.x, 16);
            vsum.y += __shfl_xor_sync(0xffffffffu, vsum.y, 16);
            vsum.z += __shfl_xor_sync(0xffffffffu, vsum.z, 16);
            vsum.w += __shfl_xor_sync(0xffffffffu, vsum.w, 16);
        }
        if (keyOff == 0) {
            #pragma unroll
            for (int qi = 0; qi < QBT; qi++)
                *(float4*)(red + (part * QBT + qi) * HD + lane16 * 4) = acc[qi];
            if (HASVM)
                *(float4*)(vred + part * HD + lane16 * 4) = vsum;
        }
        __syncthreads();
        float invLen = 1.f / (float)keyLen;
        #pragma unroll
        for (int rep = 0; rep < NREP; rep++) {
            int qi = w + rep * NWARP;
            if (qi < nq) {
                int d2 = lane;
                float sx = 0.f, sy = 0.f;
                #pragma unroll
                for (int pp = 0; pp < NWARP; pp++) {
                    float2 r = *(const float2*)(red + (pp * QBT + qi) * HD + d2 * 2);
                    sx += r.x; sy += r.y;
                }
                float invw = 1.f / wsum[qi];
                sx *= invw; sy *= invw;
                if (HASVM) {
                    float vx = 0.f, vy = 0.f;
                    #pragma unroll
                    for (int pp = 0; pp < NWARP; pp++) {
                        float2 r = *(const float2*)(vred + pp * HD + d2 * 2);
                        vx += r.x; vy += r.y;
                    }
                    sx += vx * invLen; sy += vy * invLen;
                }
                size_t o = (size_t)(base + q0 + qi) * DIM + h * HD + d2 * 2;
                split1(sx, ohi[o],     olo[o]);
                split1(sy, ohi[o + 1], olo[o + 1]);
            }
        }
    }
}

// ---------------- host ----------------
static void run_mma(const unsigned short* Ahi, const unsigned short* Alo,
                    const unsigned short* Bhi, const unsigned short* Blo,
                    const float* bias, const float* res, float* C,
                    unsigned short* Chi, unsigned short* Clo,
                    int M, int N, int K, int act) {
    dim3 grid(N / 128, (M + 63) / 64);
    mma_gemm<false><<<grid, 256, NSTG * STG>>>(Ahi, Alo, Bhi, Blo, bias, res, C, Chi, Clo, M, N, K, act);
}
static void run_mma_sk(const unsigned short* Ahi, const unsigned short* Alo,
                       const unsigned short* Bhi, const unsigned short* Blo,
                       const float* bias, float* C, int M, int N, int K, int slices) {
    dim3 grid(N / 128, (M + 63) / 64, slices);
    mma_gemm<true><<<grid, 256, NSTG * STG>>>(Ahi, Alo, Bhi, Blo, bias, nullptr, C,
                                              nullptr, nullptr, M, N, K, 0);
}

extern "C" void kernel_launch(void* const* d_in, const int* in_sizes, int n_in,
                              void* d_out, int out_size) {
    const float* x       = (const float*)d_in[0];
    const float* W_patch = (const float*)d_in[1];
    const float* b_patch = (const float*)d_in[2];
    const float* cls     = (const float*)d_in[3];
    const float* pos     = (const float*)d_in[4];
    const float* ln1_g   = (const float*)d_in[5];
    const float* ln1_b   = (const float*)d_in[6];
    const float* qkv_w   = (const float*)d_in[7];
    const float* qkv_b   = (const float*)d_in[8];
    const float* proj_w  = (const float*)d_in[9];
    const float* proj_b  = (const float*)d_in[10];
    const float* ln2_g   = (const float*)d_in[11];
    const float* ln2_b   = (const float*)d_in[12];
    const float* fc1_w   = (const float*)d_in[13];
    const float* fc1_b   = (const float*)d_in[14];
    const float* fc2_w   = (const float*)d_in[15];
    const float* fc2_b   = (const float*)d_in[16];
    const float* lnf_g   = (const float*)d_in[17];
    const float* lnf_b   = (const float*)d_in[18];

    float *emb_, *h_, *qkv_;
    unsigned short *pH, *pL, *aH, *aL, *oH, *oL, *mH, *mL;
    unsigned short *wpH, *wpL, *qkH, *qkL, *prH, *prL, *f1H, *f1L, *f2H, *f2L;
    cudaGetSymbolAddress((void**)&emb_, g_emb);
    cudaGetSymbolAddress((void**)&h_,   g_h);
    cudaGetSymbolAddress((void**)&qkv_, g_qkv);
    cudaGetSymbolAddress((void**)&pH, g_p_hi);   cudaGetSymbolAddress((void**)&pL, g_p_lo);
    cudaGetSymbolAddress((void**)&aH, g_a_hi);   cudaGetSymbolAddress((void**)&aL, g_a_lo);
    cudaGetSymbolAddress((void**)&oH, g_o_hi);   cudaGetSymbolAddress((void**)&oL, g_o_lo);
    cudaGetSymbolAddress((void**)&mH, g_m_hi);   cudaGetSymbolAddress((void**)&mL, g_m_lo);
    cudaGetSymbolAddress((void**)&wpH, g_wp_hi); cudaGetSymbolAddress((void**)&wpL, g_wp_lo);
    cudaGetSymbolAddress((void**)&qkH, g_qkvT_hi); cudaGetSymbolAddress((void**)&qkL, g_qkvT_lo);
    cudaGetSymbolAddress((void**)&prH, g_projT_hi); cudaGetSymbolAddress((void**)&prL, g_projT_lo);
    cudaGetSymbolAddress((void**)&f1H, g_fc1T_hi); cudaGetSymbolAddress((void**)&f1L, g_fc1T_lo);
    cudaGetSymbolAddress((void**)&f2H, g_fc2T_hi); cudaGetSymbolAddress((void**)&f2L, g_fc2T_lo);

    cudaFuncSetAttribute(mma_gemm<false>, cudaFuncAttributeMaxDynamicSharedMemorySize, NSTG * STG);
    cudaFuncSetAttribute(mma_gemm<true>,  cudaFuncAttributeMaxDynamicSharedMemorySize, NSTG * STG);

    size_t smem_sp = (size_t)(8 * HD + 8 * 200 + 8 * 8 * HD + 8 * HD) * sizeof(float);
    size_t smem_joint = (size_t)(16 * HD + 16 * SEQ + 16 * 16 * HD) * sizeof(float);
    cudaFuncSetAttribute((const void*)attn_kernel<16, 512, 2, false>,
                         cudaFuncAttributeMaxDynamicSharedMemorySize, (int)smem_joint);
    cudaFuncSetAttribute((const void*)attn_kernel<8, 256, 4, true>,
                         cudaFuncAttributeMaxDynamicSharedMemorySize, (int)smem_sp);

    patch_kernel<<<(1568 * 768 + 255) / 256, 256>>>(x, pH, pL);                       // 0
    split_kernel<<<(DIM * DIM + 255) / 256, 256>>>(W_patch, wpH, wpL, DIM * DIM);     // 1
    dim3 tb(32, 8);
    transpose_split_kernel<<<dim3(QKVD / 32, DIM / 32, 12), tb>>>(qkv_w, qkH, qkL, DIM, QKVD); // 2
    run_mma(pH, pL, wpH, wpL, b_patch, nullptr, emb_, nullptr, nullptr, 1568, 768, 768, 0);    // 3 <- profiled
    transpose_split_kernel<<<dim3(DIM / 32,  DIM / 32, 12), tb>>>(proj_w, prH, prL, DIM, DIM);
    transpose_split_kernel<<<dim3(MLPD / 32, DIM / 32, 12), tb>>>(fc1_w,  f1H, f1L, DIM, MLPD);
    transpose_split_kernel<<<dim3(DIM / 32, MLPD / 32, 12), tb>>>(fc2_w,  f2H, f2L, MLPD, DIM);
    assemble_kernel<<<(SEQ * DIM + 255) / 256, 256>>>(emb_, cls, pos, h_);

    for (int i = 0; i < 12; i++) {
        ln_split_kernel<<<SEQ, 256>>>(h_, ln1_g + i * DIM, ln1_b + i * DIM, aH, aL);
        run_mma(aH, aL, qkH + (size_t)i * QKVD * DIM, qkL + (size_t)i * QKVD * DIM,
                qkv_b + i * QKVD, nullptr, qkv_, nullptr, nullptr, SEQ, QKVD, DIM, 0);
        if ((i & 1) == 0) {
            dim3 g((NTOK + 7) / 8, NHEAD * TFR);
            attn_kernel<8, 256, 4, true><<<g, 256, smem_sp>>>(qkv_, oH, oL, NTOK, 200, TFR);
        } else {
            dim3 g((SEQ + 15) / 16, NHEAD);
            attn_kernel<16, 512, 2, false><<<g, 512, smem_joint>>>(qkv_, oH, oL, SEQ, SEQ, 1);
        }
        // proj: split-K=2 into h (residual already there; bias via z==0 slice)
        run_mma_sk(oH, oL, prH + (size_t)i * DIM * DIM, prL + (size_t)i * DIM * DIM,
                   proj_b + i * DIM, h_, SEQ, DIM, DIM, 2);
        ln_split_kernel<<<SEQ, 256>>>(h_, ln2_g + i * DIM, ln2_b + i * DIM, aH, aL);
        run_mma(aH, aL, f1H + (size_t)i * MLPD * DIM, f1L + (size_t)i * MLPD * DIM,
                fc1_b + i * MLPD, nullptr, nullptr, mH, mL, SEQ, MLPD, DIM, 1);
        // fc2: split-K=4 into h
        run_mma_sk(mH, mL, f2H + (size_t)i * DIM * MLPD, f2L + (size_t)i * DIM * MLPD,
                   fc2_b + i * DIM, h_, SEQ, DIM, MLPD, 4);
    }

    ln_kernel<<<SEQ, 256>>>(h_, lnf_g, lnf_b, (float*)d_out);
}

// round 17
// speedup vs baseline: 1.1098x; 1.0430x over previous
#include <cuda_runtime.h>
#include <cuda_bf16.h>
#include <math.h>
#include <stdint.h>

constexpr int SEQ  = 1576;   // T*N tokens
constexpr int DIM  = 768;
constexpr int NHEAD = 12;
constexpr int HD   = 64;
constexpr int TFR  = 8;      // frames
constexpr int NTOK = 197;    // tokens per frame
constexpr int NPAT = 196;
constexpr int MLPD = 3072;
constexpr int QKVD = 2304;
constexpr float ASCALE = 0.125f;

// ---------------- scratch (no allocation allowed) ----------------
__device__ float g_emb[1568 * 768];
__device__ float g_h[SEQ * DIM];
__device__ float g_qkv[SEQ * QKVD];
__device__ unsigned short g_qk_hi[SEQ * 1536], g_qk_lo[SEQ * 1536];
__device__ unsigned short g_p_hi[1568 * 768],  g_p_lo[1568 * 768];
__device__ unsigned short g_a_hi[SEQ * DIM],   g_a_lo[SEQ * DIM];
__device__ unsigned short g_o_hi[SEQ * DIM],   g_o_lo[SEQ * DIM];
__device__ unsigned short g_m_hi[SEQ * MLPD],  g_m_lo[SEQ * MLPD];
__device__ unsigned short g_wp_hi[DIM * DIM],        g_wp_lo[DIM * DIM];
__device__ unsigned short g_qkvT_hi[12 * QKVD * DIM], g_qkvT_lo[12 * QKVD * DIM];
__device__ unsigned short g_projT_hi[12 * DIM * DIM], g_projT_lo[12 * DIM * DIM];
__device__ unsigned short g_fc1T_hi[12 * MLPD * DIM], g_fc1T_lo[12 * MLPD * DIM];
__device__ unsigned short g_fc2T_hi[12 * DIM * MLPD], g_fc2T_lo[12 * DIM * MLPD];

// ================= helpers =================
__device__ __forceinline__ uint32_t smem_u32(const void* p) {
    uint32_t a;
    asm("{ .reg .u64 t; cvta.to.shared.u64 t, %1; cvt.u32.u64 %0, t; }" : "=r"(a) : "l"(p));
    return a;
}
__device__ __forceinline__ void split1(float v, unsigned short& hi, unsigned short& lo) {
    __nv_bfloat16 h = __float2bfloat16(v);
    __nv_bfloat16 l = __float2bfloat16(v - __bfloat162float(h));
    hi = __bfloat16_as_ushort(h);
    lo = __bfloat16_as_ushort(l);
}

#define LDM4(r, addr) \
    asm volatile("ldmatrix.sync.aligned.m8n8.x4.shared.b16 {%0,%1,%2,%3}, [%4];" \
        : "=r"((r)[0]), "=r"((r)[1]), "=r"((r)[2]), "=r"((r)[3]) : "r"(addr))

#define MMA_BF16(c, a, b0, b1) \
    asm volatile("mma.sync.aligned.m16n8k16.row.col.f32.bf16.bf16.f32 " \
        "{%0,%1,%2,%3}, {%4,%5,%6,%7}, {%8,%9}, {%0,%1,%2,%3};" \
        : "+f"((c)[0]), "+f"((c)[1]), "+f"((c)[2]), "+f"((c)[3]) \
        : "r"((a)[0]), "r"((a)[1]), "r"((a)[2]), "r"((a)[3]), "r"(b0), "r"(b1))

#define CPA16(dst, src, sz) \
    asm volatile("cp.async.cg.shared.global [%0], [%1], 16, %2;" \
        :: "r"(dst), "l"(src), "r"(sz))
#define CPA_COMMIT() asm volatile("cp.async.commit_group;")
#define CPA_WAIT1()  asm volatile("cp.async.wait_group 1;")

// ---------------- transpose + split ----------------
__global__ void transpose_split_kernel(const float* __restrict__ in,
        unsigned short* __restrict__ ohi, unsigned short* __restrict__ olo, int K, int N) {
    __shared__ float t[32][33];
    size_t base = (size_t)blockIdx.z * K * N;
    int n0 = blockIdx.x * 32, k0 = blockIdx.y * 32;
    int tx = threadIdx.x, ty = threadIdx.y;
    #pragma unroll
    for (int j = 0; j < 32; j += 8)
        t[ty + j][tx] = in[base + (size_t)(k0 + ty + j) * N + n0 + tx];
    __syncthreads();
    #pragma unroll
    for (int j = 0; j < 32; j += 8) {
        unsigned short hi, lo;
        split1(t[tx][ty + j], hi, lo);
        size_t o = base + (size_t)(n0 + ty + j) * K + k0 + tx;
        ohi[o] = hi; olo[o] = lo;
    }
}

// ---------------- elementwise split ----------------
__global__ void split_kernel(const float* __restrict__ in,
        unsigned short* __restrict__ hi, unsigned short* __restrict__ lo, int n) {
    int i = blockIdx.x * blockDim.x + threadIdx.x;
    if (i >= n) return;
    split1(in[i], hi[i], lo[i]);
}

// ---------------- split Q/K sections of qkv -> bf16 hi/lo [SEQ,1536] ----------------
__global__ void split_qk_kernel(const float* __restrict__ qkv,
        unsigned short* __restrict__ hi, unsigned short* __restrict__ lo) {
    int i = blockIdx.x * blockDim.x + threadIdx.x;
    if (i >= SEQ * 1536) return;
    int tok = i / 1536, c = i % 1536;
    split1(qkv[(size_t)tok * QKVD + c], hi[i], lo[i]);
}

// ===================================================================================
// bf16x3 MMA GEMM (unchanged best config; SK = split-K w/ atomics)
// ===================================================================================
constexpr int RS = 80;
constexpr int NSTG = 3;
constexpr int AL_OFF = 64 * RS;
constexpr int BH_OFF = 2 * 64 * RS;
constexpr int BL_OFF = BH_OFF + 128 * RS;
constexpr int STG    = BH_OFF + 2 * 128 * RS;   // 30720

__device__ __forceinline__ void load_stage(uint32_t sb,
        const unsigned short* __restrict__ Ahi, const unsigned short* __restrict__ Alo,
        const unsigned short* __restrict__ Bhi, const unsigned short* __restrict__ Blo,
        int row0, int col0, int K, int k0, int M, int tid) {
    int r = tid >> 2, ch = tid & 3;
    uint32_t doff = (uint32_t)(r * RS + ch * 16);
    size_t asrc = (size_t)(row0 + r) * K + k0 + ch * 8;
    int av = (row0 + r < M) ? 16 : 0;
    CPA16(sb + doff, Ahi + asrc, av);
    CPA16(sb + AL_OFF + doff, Alo + asrc, av);
    size_t b0 = (size_t)(col0 + r) * K + k0 + ch * 8;
    size_t b1 = (size_t)(col0 + 64 + r) * K + k0 + ch * 8;
    CPA16(sb + BH_OFF + doff, Bhi + b0, 16);
    CPA16(sb + BH_OFF + doff + 64 * RS, Bhi + b1, 16);
    CPA16(sb + BL_OFF + doff, Blo + b0, 16);
    CPA16(sb + BL_OFF + doff + 64 * RS, Blo + b1, 16);
    CPA_COMMIT();
}

template <bool SK>
__global__ void __launch_bounds__(256, 2) mma_gemm(
        const unsigned short* __restrict__ Ahi, const unsigned short* __restrict__ Alo,
        const unsigned short* __restrict__ Bhi, const unsigned short* __restrict__ Blo,
        const float* __restrict__ bias, const float* __restrict__ res,
        float* __restrict__ C, unsigned short* __restrict__ Chi,
        unsigned short* __restrict__ Clo,
        int M, int N, int K, int act) {
    extern __shared__ __align__(128) char sm[];
    const int tid = threadIdx.x;
    const int lane = tid & 31, wid = tid >> 5;
    const int wm = wid & 1, wn = wid >> 1;
    const int row0 = blockIdx.y * 64, col0 = blockIdx.x * 128;
    const uint32_t smb = smem_u32(sm);

    const int a_row = ((lane >> 3) & 1) * 8 + (lane & 7);
    const int a_kb  = (lane >> 4) * 16;
    const int b_row = (lane >> 4) * 8 + (lane & 7);
    const int b_kb  = ((lane >> 3) & 1) * 16;

    float c[2][4][4];
    #pragma unroll
    for (int i = 0; i < 2; i++)
        #pragma unroll
        for (int j = 0; j < 4; j++)
            #pragma unroll
            for (int k = 0; k < 4; k++) c[i][j][k] = 0.f;

    const int klen  = SK ? (K / gridDim.z) : K;
    const int kbase = SK ? blockIdx.z * klen : 0;
    const int nk = klen >> 5;
    load_stage(smb, Ahi, Alo, Bhi, Blo, row0, col0, K, kbase, M, tid);
    load_stage(smb + STG, Ahi, Alo, Bhi, Blo, row0, col0, K, kbase + 32, M, tid);

    int buf = 0;
    for (int it = 0; it < nk; it++) {
        CPA_WAIT1();
        __syncthreads();
        if (it + 2 < nk) {
            int nb = buf + 2; if (nb >= NSTG) nb -= NSTG;
            load_stage(smb + (uint32_t)nb * STG, Ahi, Alo, Bhi, Blo,
                       row0, col0, K, kbase + ((it + 2) << 5), M, tid);
        }
        uint32_t sb = smb + (uint32_t)buf * STG;
        #pragma unroll
        for (int kk = 0; kk < 2; kk++) {
            uint32_t bh[8], bl[8];
            #pragma unroll
            for (int nip = 0; nip < 2; nip++) {
                uint32_t baddr = sb + BH_OFF + (wn * 32 + nip * 16 + b_row) * RS + b_kb + kk * 32;
                LDM4(&bh[nip * 4], baddr);
                LDM4(&bl[nip * 4], baddr + (BL_OFF - BH_OFF));
            }
            #pragma unroll
            for (int mi = 0; mi < 2; mi++) {
                uint32_t ah[4], al[4];
                uint32_t aaddr = sb + (wm * 32 + mi * 16 + a_row) * RS + a_kb + kk * 32;
                LDM4(ah, aaddr);
                LDM4(al, aaddr + AL_OFF);
                #pragma unroll
                for (int ni = 0; ni < 4; ni++) {
                    uint32_t b0h = bh[(ni >> 1) * 4 + (ni & 1) * 2];
                    uint32_t b1h = bh[(ni >> 1) * 4 + (ni & 1) * 2 + 1];
                    uint32_t b0l = bl[(ni >> 1) * 4 + (ni & 1) * 2];
                    uint32_t b1l = bl[(ni >> 1) * 4 + (ni & 1) * 2 + 1];
                    MMA_BF16(c[mi][ni], ah, b0h, b1h);
                    MMA_BF16(c[mi][ni], ah, b0l, b1l);
                    MMA_BF16(c[mi][ni], al, b0h, b1h);
                }
            }
        }
        buf++; if (buf >= NSTG) buf = 0;
    }

    const int g = lane >> 2, t = lane & 3;
    #pragma unroll
    for (int mi = 0; mi < 2; mi++) {
        #pragma unroll
        for (int ni = 0; ni < 4; ni++) {
            int col = col0 + wn * 32 + ni * 8 + t * 2;
            float2 bb = (bias && (!SK || blockIdx.z == 0))
                        ? *(const float2*)(bias + col) : make_float2(0.f, 0.f);
            #pragma unroll
            for (int half = 0; half < 2; half++) {
                int gm = row0 + wm * 32 + mi * 16 + g + half * 8;
                if (gm >= M) continue;
                float v0 = c[mi][ni][half * 2 + 0] + bb.x;
                float v1 = c[mi][ni][half * 2 + 1] + bb.y;
                size_t o = (size_t)gm * N + col;
                if (SK) {
                    atomicAdd(C + o, v0);
                    atomicAdd(C + o + 1, v1);
                } else {
                    if (act) {
                        v0 = 0.5f * v0 * (1.f + erff(v0 * 0.70710678118f));
                        v1 = 0.5f * v1 * (1.f + erff(v1 * 0.70710678118f));
                    }
                    if (res) {
                        float2 rv = *(const float2*)(res + o);
                        v0 += rv.x; v1 += rv.y;
                    }
                    if (Chi) {
                        unsigned short h0, l0, h1, l1;
                        split1(v0, h0, l0);
                        split1(v1, h1, l1);
                        *(uint32_t*)(Chi + o) = (uint32_t)h0 | ((uint32_t)h1 << 16);
                        *(uint32_t*)(Clo + o) = (uint32_t)l0 | ((uint32_t)l1 << 16);
                    } else {
                        *(float2*)(C + o) = make_float2(v0, v1);
                    }
                }
            }
        }
    }
}

// ---------------- patch extraction -> bf16 hi/lo ----------------
__global__ void patch_kernel(const float* __restrict__ x,
        unsigned short* __restrict__ Phi, unsigned short* __restrict__ Plo) {
    int idx = blockIdx.x * blockDim.x + threadIdx.x;
    if (idx >= 1568 * 768) return;
    int m = idx / 768, kcol = idx % 768;
    int t = m / 196, n = m % 196;
    int hp = n / 14, wp = n % 14;
    int c = kcol / 256, rem = kcol % 256;
    int ii = rem / 16, jj = rem % 16;
    float v = x[((t * 3 + c) * 224 + hp * 16 + ii) * 224 + wp * 16 + jj];
    split1(v, Phi[idx], Plo[idx]);
}

// ---------------- assemble h ----------------
__global__ void assemble_kernel(const float* __restrict__ emb, const float* __restrict__ cls,
                                const float* __restrict__ pos, float* __restrict__ h) {
    int idx = blockIdx.x * blockDim.x + threadIdx.x;
    if (idx >= SEQ * DIM) return;
    int m = idx / DIM, dd = idx % DIM;
    int t = m / NTOK, r = m % NTOK;
    float v;
    if (r == 0) {
        v = cls[dd] + pos[dd];
    } else {
        int pp = r - 1;
        int f = pp * DIM + dd;
        int n = f % NPAT, dc = f / NPAT;
        v = emb[(t * NPAT + n) * DIM + dc] + pos[(1 + pp) * DIM + dd];
    }
    h[idx] = v;
}

// ---------------- block reduction ----------------
__device__ __forceinline__ float block_sum256(float v, float* sh) {
    #pragma unroll
    for (int o = 16; o; o >>= 1) v += __shfl_xor_sync(0xffffffffu, v, o);
    if ((threadIdx.x & 31) == 0) sh[threadIdx.x >> 5] = v;
    __syncthreads();
    float t = 0.f;
    #pragma unroll
    for (int i = 0; i < 8; i++) t += sh[i];
    __syncthreads();
    return t;
}

// ---------------- LayerNorm -> bf16 hi/lo ----------------
__global__ void ln_split_kernel(const float* __restrict__ x, const float* __restrict__ g,
        const float* __restrict__ b, unsigned short* __restrict__ yhi,
        unsigned short* __restrict__ ylo) {
    __shared__ float sh[8];
    int row = blockIdx.x, tid = threadIdx.x;
    const float* xr = x + (size_t)row * DIM;
    float v0 = xr[tid], v1 = xr[tid + 256], v2 = xr[tid + 512];
    float mean = block_sum256(v0 + v1 + v2, sh) * (1.f / DIM);
    float d0 = v0 - mean, d1 = v1 - mean, d2 = v2 - mean;
    float var = block_sum256(d0 * d0 + d1 * d1 + d2 * d2, sh) * (1.f / DIM);
    float inv = rsqrtf(var + 1e-5f);
    size_t o = (size_t)row * DIM + tid;
    float y0 = d0 * inv * g[tid]       + b[tid];
    float y1 = d1 * inv * g[tid + 256] + b[tid + 256];
    float y2 = d2 * inv * g[tid + 512] + b[tid + 512];
    split1(y0, yhi[o],       ylo[o]);
    split1(y1, yhi[o + 256], ylo[o + 256]);
    split1(y2, yhi[o + 512], ylo[o + 512]);
}

// ---------------- final LayerNorm (fp32 out) ----------------
__global__ void ln_kernel(const float* __restrict__ x, const float* __restrict__ g,
                          const float* __restrict__ b, float* __restrict__ y) {
    __shared__ float sh[8];
    int row = blockIdx.x, tid = threadIdx.x;
    const float* xr = x + (size_t)row * DIM;
    float v0 = xr[tid], v1 = xr[tid + 256], v2 = xr[tid + 512];
    float mean = block_sum256(v0 + v1 + v2, sh) * (1.f / DIM);
    float d0 = v0 - mean, d1 = v1 - mean, d2 = v2 - mean;
    float var = block_sum256(d0 * d0 + d1 * d1 + d2 * d2, sh) * (1.f / DIM);
    float inv = rsqrtf(var + 1e-5f);
    float* yr = y + (size_t)row * DIM;
    yr[tid]       = d0 * inv * g[tid]       + b[tid];
    yr[tid + 256] = d1 * inv * g[tid + 256] + b[tid + 256];
    yr[tid + 512] = d2 * inv * g[tid + 512] + b[tid + 512];
}

// ---------------- attention, templated ----------
// MMASC: score phase via bf16x3 mma (needs qkh/qkl pre-split Q/K), joint layers.
// else: fp32 KCH-register-blocked scores (spatial layers, with fused v-mean).
constexpr int QRS = 144;           // bf16 smem row stride (conflict-free ldmatrix)
template <int QBT, int NTHR, int KCH, bool HASVM, bool MMASC>
__global__ void __launch_bounds__(NTHR) attn_kernel(
        const float* __restrict__ qkv,
        const unsigned short* __restrict__ qkh, const unsigned short* __restrict__ qkl,
        unsigned short* __restrict__ ohi, unsigned short* __restrict__ olo,
        int keyLen, int keyLenP, int numSeg) {
    constexpr int NWARP = NTHR / 32;
    constexpr int NREP  = (QBT + NWARP - 1) / NWARP;
    extern __shared__ float smf[];
    __shared__ float wsum[QBT];
    int tid = threadIdx.x;
    int hseg = blockIdx.y;
    int h = hseg / numSeg, seg = hseg % numSeg;
    int base = seg * keyLen;
    int q0 = blockIdx.x * QBT;
    int nq = min(QBT, keyLen - q0);
    int w = tid >> 5, lane = tid & 31;

    float* qs;
    float* sc;
    float* red;
    float* vred = nullptr;
    if (MMASC) {
        qs  = nullptr;
        sc  = (float*)((char*)smf + 2 * QBT * QRS);          // after bf16 Q (hi+lo)
        red = sc + QBT * keyLenP;                             // aliased with K tile
    } else {
        qs  = smf;
        sc  = smf + QBT * HD;
        red = sc + QBT * keyLenP;
        vred = red + NWARP * QBT * HD;
    }

    if (MMASC) {
        // ---- stage Q block bf16 hi/lo ----
        char* smq = (char*)smf;
        for (int i = tid; i < QBT * HD; i += NTHR) {
            int qi = i / HD, d = i % HD;
            unsigned short hv = 0, lv = 0;
            if (qi < nq) {
                size_t s = (size_t)(base + q0 + qi) * 1536 + h * HD + d;
                hv = qkh[s]; lv = qkl[s];
            }
            *(unsigned short*)(smq + qi * QRS + d * 2) = hv;
            *(unsigned short*)(smq + QBT * QRS + qi * QRS + d * 2) = lv;
        }
        // ---- scores via MMA, 256-key chunks, warp = 16 keys ----
        char* smk = (char*)red;                   // K tile aliases red
        const int KLO = 256 * QRS;
        const uint32_t smqb = smem_u32(smq);
        const uint32_t smkb = smem_u32(smk);
        const int a_row = ((lane >> 3) & 1) * 8 + (lane & 7);
        const int a_kb  = (lane >> 4) * 16;
        const int b_row = (lane >> 4) * 8 + (lane & 7);
        const int b_kb  = ((lane >> 3) & 1) * 16;
        const int g = lane >> 2, t = lane & 3;
        for (int kb = 0; kb < keyLen; kb += 256) {
            __syncthreads();
            for (int i = tid; i < 2048; i += NTHR) {
                int key = i >> 3, segi = i & 7;
                int gk = kb + key;
                uint4 vh = make_uint4(0, 0, 0, 0), vl = make_uint4(0, 0, 0, 0);
                if (gk < keyLen) {
                    size_t s = (size_t)(base + gk) * 1536 + 768 + h * HD + segi * 8;
                    vh = *(const uint4*)(qkh + s);
                    vl = *(const uint4*)(qkl + s);
                }
                *(uint4*)(smk + key * QRS + segi * 16) = vh;
                *(uint4*)(smk + KLO + key * QRS + segi * 16) = vl;
            }
            __syncthreads();
            int wkb = kb + w * 16;
            if (wkb < keyLen) {
                float cc[2][4];
                #pragma unroll
                for (int ni = 0; ni < 2; ni++)
                    #pragma unroll
                    for (int k = 0; k < 4; k++) cc[ni][k] = 0.f;
                #pragma unroll
                for (int kk = 0; kk < 4; kk++) {
                    uint32_t ah[4], al[4], bh[4], bl[4];
                    uint32_t aaddr = smqb + a_row * QRS + a_kb + kk * 32;
                    LDM4(ah, aaddr);
                    LDM4(al, aaddr + QBT * QRS);
                    uint32_t baddr = smkb + (w * 16 + b_row) * QRS + b_kb + kk * 32;
                    LDM4(bh, baddr);
                    LDM4(bl, baddr + KLO);
                    #pragma unroll
                    for (int ni = 0; ni < 2; ni++) {
                        MMA_BF16(cc[ni], ah, bh[ni * 2], bh[ni * 2 + 1]);
                        MMA_BF16(cc[ni], ah, bl[ni * 2], bl[ni * 2 + 1]);
                        MMA_BF16(cc[ni], al, bh[ni * 2], bh[ni * 2 + 1]);
                    }
                }
                #pragma unroll
                for (int ni = 0; ni < 2; ni++)
                    #pragma unroll
                    for (int half = 0; half < 2; half++)
                        #pragma unroll
                        for (int j = 0; j < 2; j++) {
                            int key = wkb + ni * 8 + t * 2 + j;
                            if (key < keyLen)
                                sc[(g + half * 8) * keyLenP + key] =
                                    cc[ni][half * 2 + j] * ASCALE;
                        }
            }
        }
        __syncthreads();
    } else {
        for (int i = tid; i < QBT * HD; i += NTHR) {
            int qi = i / HD, d = i % HD;
            qs[i] = (qi < nq) ? qkv[(size_t)(base + q0 + qi) * QKVD + h * HD + d] : 0.f;
        }
        __syncthreads();
        const int nkb = (keyLen + KCH - 1) / KCH;
        for (int kb = tid; kb < nkb; kb += NTHR) {
            int kk = kb * KCH;
            float acc[QBT][KCH];
            #pragma unroll
            for (int qi = 0; qi < QBT; qi++)
                #pragma unroll
                for (int c = 0; c < KCH; c++) acc[qi][c] = 0.f;
            const float* kbase0 = qkv + (size_t)(base + kk) * QKVD + DIM + h * HD;
            int voff[KCH];
            #pragma unroll
            for (int c = 0; c < KCH; c++) voff[c] = (kk + c < keyLen) ? c : 0;
            #pragma unroll 4
            for (int j = 0; j < 16; j++) {
                float4 kf[KCH];
                #pragma unroll
                for (int c = 0; c < KCH; c++)
                    kf[c] = *(const float4*)(kbase0 + (size_t)voff[c] * QKVD + j * 4);
                #pragma unroll
                for (int qi = 0; qi < QBT; qi++) {
                    float4 q = *(const float4*)(qs + qi * HD + j * 4);
                    #pragma unroll
                    for (int c = 0; c < KCH; c++)
                        acc[qi][c] += q.x * kf[c].x + q.y * kf[c].y
                                    + q.z * kf[c].z + q.w * kf[c].w;
                }
            }
            #pragma unroll
            for (int qi = 0; qi < QBT; qi++) {
                float* dst = sc + qi * keyLenP + kk;
                if (kk + KCH <= keyLen) {
                    #pragma unroll
                    for (int c = 0; c < KCH; c++) dst[c] = acc[qi][c] * ASCALE;
                } else {
                    for (int c = 0; c < KCH; c++)
                        if (kk + c < keyLen) dst[c] = acc[qi][c] * ASCALE;
                }
            }
        }
        __syncthreads();
    }

    // ---- softmax ----
    #pragma unroll
    for (int rep = 0; rep < NREP; rep++) {
        int q = w + rep * NWARP;
        if (q < nq) {
            float mx = -1e30f;
            for (int kk = lane; kk < keyLen; kk += 32) mx = fmaxf(mx, sc[q * keyLenP + kk]);
            #pragma unroll
            for (int off = 16; off; off >>= 1) mx = fmaxf(mx, __shfl_xor_sync(0xffffffffu, mx, off));
            float sum = 0.f;
            for (int kk = lane; kk < keyLen; kk += 32) {
                float e = __expf(sc[q * keyLenP + kk] - mx);
                sc[q * keyLenP + kk] = e;
                sum += e;
            }
            #pragma unroll
            for (int off = 16; off; off >>= 1) sum += __shfl_xor_sync(0xffffffffu, sum, off);
            if (lane == 0) wsum[q] = sum;
        }
    }
    __syncthreads();

    // ---- AV: 2 keys per warp per iter, float4 V, half-warps combined by shfl ----
    {
        int lane16 = lane & 15;
        int keyOff = lane >> 4;
        int part = w;
        float4 acc[QBT];
        #pragma unroll
        for (int qi = 0; qi < QBT; qi++) acc[qi] = make_float4(0.f, 0.f, 0.f, 0.f);
        float4 vsum = make_float4(0.f, 0.f, 0.f, 0.f);
        const float* vbase = qkv + 2 * DIM + h * HD + lane16 * 4;
        for (int kk = part * 2 + keyOff; kk < keyLen; kk += 2 * NWARP) {
            float4 v = *(const float4*)(vbase + (size_t)(base + kk) * QKVD);
            if (HASVM) { vsum.x += v.x; vsum.y += v.y; vsum.z += v.z; vsum.w += v.w; }
            #pragma unroll
            for (int qi = 0; qi < QBT; qi++) {
                float p = sc[qi * keyLenP + kk];
                acc[qi].x += p * v.x; acc[qi].y += p * v.y;
                acc[qi].z += p * v.z; acc[qi].w += p * v.w;
            }
        }
        #pragma unroll
        for (int qi = 0; qi < QBT; qi++) {
            acc[qi].x += __shfl_xor_sync(0xffffffffu, acc[qi].x, 16);
            acc[qi].y += __shfl_xor_sync(0xffffffffu, acc[qi].y, 16);
            acc[qi].z += __shfl_xor_sync(0xffffffffu, acc[qi].z, 16);
            acc[qi].w += __shfl_xor_sync(0xffffffffu, acc[qi].w, 16);
        }
        if (HASVM) {
            vsum.x += __shfl_xor_sync(0xffffffffu, vsum.x, 16);
            vsum.y += __shfl_xor_sync(0xffffffffu, vsum.y, 16);
            vsum.z += __shfl_xor_sync(0xffffffffu, vsum.z, 16);
            vsum.w += __shfl_xor_sync(0xffffffffu, vsum.w, 16);
        }
        __syncthreads();   // K-tile/red alias: ensure score phase fully done on all warps
        if (keyOff == 0) {
            #pragma unroll
            for (int qi = 0; qi < QBT; qi++)
                *(float4*)(red + (part * QBT + qi) * HD + lane16 * 4) = acc[qi];
            if (HASVM)
                *(float4*)(vred + part * HD + lane16 * 4) = vsum;
        }
        __syncthreads();
        float invLen = 1.f / (float)keyLen;
        #pragma unroll
        for (int rep = 0; rep < NREP; rep++) {
            int qi = w + rep * NWARP;
            if (qi < nq) {
                int d2 = lane;
                float sx = 0.f, sy = 0.f;
                #pragma unroll
                for (int pp = 0; pp < NWARP; pp++) {
                    float2 r = *(const float2*)(red + (pp * QBT + qi) * HD + d2 * 2);
                    sx += r.x; sy += r.y;
                }
                float invw = 1.f / wsum[qi];
                sx *= invw; sy *= invw;
                if (HASVM) {
                    float vx = 0.f, vy = 0.f;
                    #pragma unroll
                    for (int pp = 0; pp < NWARP; pp++) {
                        float2 r = *(const float2*)(vred + pp * HD + d2 * 2);
                        vx += r.x; vy += r.y;
                    }
                    sx += vx * invLen; sy += vy * invLen;
                }
                size_t o = (size_t)(base + q0 + qi) * DIM + h * HD + d2 * 2;
                split1(sx, ohi[o],     olo[o]);
                split1(sy, ohi[o + 1], olo[o + 1]);
            }
        }
    }
}

// ---------------- host ----------------
static void run_mma(const unsigned short* Ahi, const unsigned short* Alo,
                    const unsigned short* Bhi, const unsigned short* Blo,
                    const float* bias, const float* res, float* C,
                    unsigned short* Chi, unsigned short* Clo,
                    int M, int N, int K, int act) {
    dim3 grid(N / 128, (M + 63) / 64);
    mma_gemm<false><<<grid, 256, NSTG * STG>>>(Ahi, Alo, Bhi, Blo, bias, res, C, Chi, Clo, M, N, K, act);
}
static void run_mma_sk(const unsigned short* Ahi, const unsigned short* Alo,
                       const unsigned short* Bhi, const unsigned short* Blo,
                       const float* bias, float* C, int M, int N, int K, int slices) {
    dim3 grid(N / 128, (M + 63) / 64, slices);
    mma_gemm<true><<<grid, 256, NSTG * STG>>>(Ahi, Alo, Bhi, Blo, bias, nullptr, C,
                                              nullptr, nullptr, M, N, K, 0);
}

extern "C" void kernel_launch(void* const* d_in, const int* in_sizes, int n_in,
                              void* d_out, int out_size) {
    const float* x       = (const float*)d_in[0];
    const float* W_patch = (const float*)d_in[1];
    const float* b_patch = (const float*)d_in[2];
    const float* cls     = (const float*)d_in[3];
    const float* pos     = (const float*)d_in[4];
    const float* ln1_g   = (const float*)d_in[5];
    const float* ln1_b   = (const float*)d_in[6];
    const float* qkv_w   = (const float*)d_in[7];
    const float* qkv_b   = (const float*)d_in[8];
    const float* proj_w  = (const float*)d_in[9];
    const float* proj_b  = (const float*)d_in[10];
    const float* ln2_g   = (const float*)d_in[11];
    const float* ln2_b   = (const float*)d_in[12];
    const float* fc1_w   = (const float*)d_in[13];
    const float* fc1_b   = (const float*)d_in[14];
    const float* fc2_w   = (const float*)d_in[15];
    const float* fc2_b   = (const float*)d_in[16];
    const float* lnf_g   = (const float*)d_in[17];
    const float* lnf_b   = (const float*)d_in[18];

    float *emb_, *h_, *qkv_;
    unsigned short *qkH_, *qkL_;
    unsigned short *pH, *pL, *aH, *aL, *oH, *oL, *mH, *mL;
    unsigned short *wpH, *wpL, *qkH, *qkL, *prH, *prL, *f1H, *f1L, *f2H, *f2L;
    cudaGetSymbolAddress((void**)&emb_, g_emb);
    cudaGetSymbolAddress((void**)&h_,   g_h);
    cudaGetSymbolAddress((void**)&qkv_, g_qkv);
    cudaGetSymbolAddress((void**)&qkH_, g_qk_hi);  cudaGetSymbolAddress((void**)&qkL_, g_qk_lo);
    cudaGetSymbolAddress((void**)&pH, g_p_hi);   cudaGetSymbolAddress((void**)&pL, g_p_lo);
    cudaGetSymbolAddress((void**)&aH, g_a_hi);   cudaGetSymbolAddress((void**)&aL, g_a_lo);
    cudaGetSymbolAddress((void**)&oH, g_o_hi);   cudaGetSymbolAddress((void**)&oL, g_o_lo);
    cudaGetSymbolAddress((void**)&mH, g_m_hi);   cudaGetSymbolAddress((void**)&mL, g_m_lo);
    cudaGetSymbolAddress((void**)&wpH, g_wp_hi); cudaGetSymbolAddress((void**)&wpL, g_wp_lo);
    cudaGetSymbolAddress((void**)&qkH, g_qkvT_hi); cudaGetSymbolAddress((void**)&qkL, g_qkvT_lo);
    cudaGetSymbolAddress((void**)&prH, g_projT_hi); cudaGetSymbolAddress((void**)&prL, g_projT_lo);
    cudaGetSymbolAddress((void**)&f1H, g_fc1T_hi); cudaGetSymbolAddress((void**)&f1L, g_fc1T_lo);
    cudaGetSymbolAddress((void**)&f2H, g_fc2T_hi); cudaGetSymbolAddress((void**)&f2L, g_fc2T_lo);

    cudaFuncSetAttribute(mma_gemm<false>, cudaFuncAttributeMaxDynamicSharedMemorySize, NSTG * STG);
    cudaFuncSetAttribute(mma_gemm<true>,  cudaFuncAttributeMaxDynamicSharedMemorySize, NSTG * STG);

    // spatial: QBT=8, 256 thr, KCH=4, HASVM, fp32 scores
    size_t smem_sp = (size_t)(8 * HD + 8 * 200 + 8 * 8 * HD + 8 * HD) * sizeof(float);
    // joint: QBT=16, 512 thr, MMA scores: Qbf16(2*16*144) + sc(16*SEQ*4) + union(K tile 2*256*144 | red 16*16*64*4)
    size_t smem_joint = 2 * 16 * QRS + (size_t)16 * SEQ * 4 + 2 * 256 * QRS;  // 179200
    cudaFuncSetAttribute((const void*)attn_kernel<16, 512, 2, false, true>,
                         cudaFuncAttributeMaxDynamicSharedMemorySize, (int)smem_joint);
    cudaFuncSetAttribute((const void*)attn_kernel<8, 256, 4, true, false>,
                         cudaFuncAttributeMaxDynamicSharedMemorySize, (int)smem_sp);

    patch_kernel<<<(1568 * 768 + 255) / 256, 256>>>(x, pH, pL);                       // 0
    split_kernel<<<(DIM * DIM + 255) / 256, 256>>>(W_patch, wpH, wpL, DIM * DIM);     // 1
    dim3 tb(32, 8);
    transpose_split_kernel<<<dim3(QKVD / 32, DIM / 32, 12), tb>>>(qkv_w, qkH, qkL, DIM, QKVD); // 2
    run_mma(pH, pL, wpH, wpL, b_patch, nullptr, emb_, nullptr, nullptr, 1568, 768, 768, 0);    // 3 <- profiled
    transpose_split_kernel<<<dim3(DIM / 32,  DIM / 32, 12), tb>>>(proj_w, prH, prL, DIM, DIM);
    transpose_split_kernel<<<dim3(MLPD / 32, DIM / 32, 12), tb>>>(fc1_w,  f1H, f1L, DIM, MLPD);
    transpose_split_kernel<<<dim3(DIM / 32, MLPD / 32, 12), tb>>>(fc2_w,  f2H, f2L, MLPD, DIM);
    assemble_kernel<<<(SEQ * DIM + 255) / 256, 256>>>(emb_, cls, pos, h_);

    for (int i = 0; i < 12; i++) {
        ln_split_kernel<<<SEQ, 256>>>(h_, ln1_g + i * DIM, ln1_b + i * DIM, aH, aL);
        run_mma(aH, aL, qkH + (size_t)i * QKVD * DIM, qkL + (size_t)i * QKVD * DIM,
                qkv_b + i * QKVD, nullptr, qkv_, nullptr, nullptr, SEQ, QKVD, DIM, 0);
        if ((i & 1) == 0) {
            dim3 g((NTOK + 7) / 8, NHEAD * TFR);
            attn_kernel<8, 256, 4, true, false><<<g, 256, smem_sp>>>(
                qkv_, nullptr, nullptr, oH, oL, NTOK, 200, TFR);
        } else {
            split_qk_kernel<<<(SEQ * 1536 + 255) / 256, 256>>>(qkv_, qkH_, qkL_);
            dim3 g((SEQ + 15) / 16, NHEAD);
            attn_kernel<16, 512, 2, false, true><<<g, 512, smem_joint>>>(
                qkv_, qkH_, qkL_, oH, oL, SEQ, SEQ, 1);
        }
        run_mma_sk(oH, oL, prH + (size_t)i * DIM * DIM, prL + (size_t)i * DIM * DIM,
                   proj_b + i * DIM, h_, SEQ, DIM, DIM, 2);
        ln_split_kernel<<<SEQ, 256>>>(h_, ln2_g + i * DIM, ln2_b + i * DIM, aH, aL);
        run_mma(aH, aL, f1H + (size_t)i * MLPD * DIM, f1L + (size_t)i * MLPD * DIM,
                fc1_b + i * MLPD, nullptr, nullptr, mH, mL, SEQ, MLPD, DIM, 1);
        run_mma_sk(mH, mL, f2H + (size_t)i * DIM * MLPD, f2L + (size_t)i * DIM * MLPD,
                   fc2_b + i * DIM, h_, SEQ, DIM, MLPD, 4);
    }

    ln_kernel<<<SEQ, 256>>>(h_, lnf_g, lnf_b, (float*)d_out);
}